// round 11
// baseline (speedup 1.0000x reference)
#include <cuda_runtime.h>
#include <cuda_bf16.h>
#include <math.h>
#include <stdint.h>

// Problem constants
#define S_LEN 2048
#define D_DIM 768
#define N_STATE 16
#define N_HEADS 12
#define DH 64
#define WINDOW 128
#define KK 1843            // int((1-0.1)*2048)
#define SPIKE 0.1f
#define FULLM 0xffffffffu

// ---------------------------------------------------------------------------
// Scratch (device globals; no dynamic allocation allowed)
// ---------------------------------------------------------------------------
__device__ float g_gate[S_LEN * D_DIM];
__device__ uint2 g_xs[S_LEN * D_DIM];          // x pre-split
__device__ uint2 g_Hs[S_LEN * D_DIM];          // H pre-split (ssm epilogue)
__device__ uint2 g_Qs[S_LEN * D_DIM];
__device__ uint2 g_Ks[S_LEN * D_DIM];
__device__ uint2 g_Vs[S_LEN * D_DIM];
__device__ uint2 g_Ws[5 * D_DIM * D_DIM];      // Wg,Wq,Wk,Wv,Wd pre-split
__device__ float g_ctx[S_LEN * D_DIM];
__device__ float g_scores[(size_t)N_HEADS * S_LEN * S_LEN];   // 192 MB

// ---------------------------------------------------------------------------
// Split-TF32 helpers (3-MMA emulation of fp32 GEMM on tensor cores)
// ---------------------------------------------------------------------------
__device__ __forceinline__ void split_tf32(float a, uint32_t& hi, uint32_t& lo) {
    asm("cvt.rna.tf32.f32 %0, %1;" : "=r"(hi) : "f"(a));
    float r = a - __uint_as_float(hi);
    asm("cvt.rna.tf32.f32 %0, %1;" : "=r"(lo) : "f"(r));
}

__device__ __forceinline__ void mma8(float c[4], const uint32_t a[4], const uint32_t b[2]) {
    asm("mma.sync.aligned.m16n8k8.row.col.f32.tf32.tf32.f32 "
        "{%0,%1,%2,%3},{%4,%5,%6,%7},{%8,%9},{%0,%1,%2,%3};"
        : "+f"(c[0]), "+f"(c[1]), "+f"(c[2]), "+f"(c[3])
        : "r"(a[0]), "r"(a[1]), "r"(a[2]), "r"(a[3]), "r"(b[0]), "r"(b[1]));
}

#define CPA16(dst, src) asm volatile("cp.async.ca.shared.global [%0], [%1], 16;" :: "r"(dst), "l"(src))
#define CPCOMMIT()      asm volatile("cp.async.commit_group;" ::: "memory")
#define CPWAIT1()       asm volatile("cp.async.wait_group 1;" ::: "memory")
#define CPWAIT0()       asm volatile("cp.async.wait_group 0;" ::: "memory")

// ---------------------------------------------------------------------------
// Pre-split kernel: 6 fp32 arrays -> interleaved (hi,lo) uint2 arrays.
// blockIdx.y selects array; 4 elements per thread.
// ---------------------------------------------------------------------------
__global__ __launch_bounds__(256)
void split6(const float* __restrict__ p0, const float* __restrict__ p1,
            const float* __restrict__ p2, const float* __restrict__ p3,
            const float* __restrict__ p4, const float* __restrict__ p5,
            uint2* __restrict__ o0, uint2* __restrict__ o1,
            uint2* __restrict__ o2, uint2* __restrict__ o3,
            uint2* __restrict__ o4, uint2* __restrict__ o5)
{
    int sel = blockIdx.y;
    const float* p = sel == 0 ? p0 : sel == 1 ? p1 : sel == 2 ? p2
                   : sel == 3 ? p3 : sel == 4 ? p4 : p5;
    uint2* o = sel == 0 ? o0 : sel == 1 ? o1 : sel == 2 ? o2
             : sel == 3 ? o3 : sel == 4 ? o4 : o5;
    int n = (sel == 0) ? S_LEN * D_DIM : D_DIM * D_DIM;
    int i = (blockIdx.x * 256 + threadIdx.x) * 4;
    if (i >= n) return;
    float4 v = *(const float4*)&p[i];
    uint32_t h, l;
    split_tf32(v.x, h, l); o[i + 0] = make_uint2(h, l);
    split_tf32(v.y, h, l); o[i + 1] = make_uint2(h, l);
    split_tf32(v.z, h, l); o[i + 2] = make_uint2(h, l);
    split_tf32(v.w, h, l); o[i + 3] = make_uint2(h, l);
}

// ---------------------------------------------------------------------------
// Unified tensor-core GEMM (split tf32, 3-MMA).
//   BT=true : C[m,n] = alpha*sum_k A[m,k]*B[n,k];  BT=false: B[k,n]
//   AS/BS: operand is pre-split uint2 (hi,lo); else fp32 split in-loop
//   OS: write C as pre-split uint2;  EPI: 0 none, 1 +bias, 2 sigmoid, 3 atomicAdd
// Tiles BM=BN=64, BK=32; 256 thr, 8 warps (2m x 4n).
// 2-stage cp.async pipeline; dynamic smem. B/bias/C selected by blockIdx.x/nper.
// band>0 limits k to row0+band; SPLITK parts via blockIdx.z.
// ---------------------------------------------------------------------------
template<bool BT, bool AS, bool BS, bool OS, int EPI, int SPLITK>
struct GP {
    static const int SA = AS ? 64 * 34 * 8 : 64 * 36 * 4;
    static const int SB = BT ? (BS ? 64 * 34 * 8 : 64 * 36 * 4)
                             : (BS ? 32 * 66 * 8 : 32 * 72 * 4);
    static const int SMEM = 2 * (SA + SB);
};

template<bool BT, bool AS, bool BS, bool OS, int EPI, int SPLITK>
__global__ __launch_bounds__(256)
void gemm_tc(const void* __restrict__ Av,
             const void* __restrict__ Bv0, const void* __restrict__ Bv1,
             const void* __restrict__ Bv2,
             const float* __restrict__ bi0, const float* __restrict__ bi1,
             const float* __restrict__ bi2,
             void* __restrict__ Cv0, void* __restrict__ Cv1, void* __restrict__ Cv2,
             int K, int lda, int ldb, int ldc,
             long Astride, long Bstride, long Cstride,
             float alpha, int band, int nper)
{
    extern __shared__ char smraw[];
    const int SA = GP<BT,AS,BS,OS,EPI,SPLITK>::SA;
    const int SB = GP<BT,AS,BS,OS,EPI,SPLITK>::SB;
    char* smA = smraw;
    char* smB = smraw + 2 * SA;

    int bz   = blockIdx.z / SPLITK;
    int part = blockIdx.z % SPLITK;
    int sel  = blockIdx.x / nper;
    int xb   = blockIdx.x % nper;

    const void* Bv    = (sel == 0) ? Bv0 : (sel == 1) ? Bv1 : Bv2;
    const float* bias = (sel == 0) ? bi0 : (sel == 1) ? bi1 : bi2;
    void* Cv          = (sel == 0) ? Cv0 : (sel == 1) ? Cv1 : Cv2;

    const uint2* A2 = (const uint2*)Av + (AS ? (long)bz * Astride : 0);
    const float* Af = (const float*)Av + (AS ? 0 : (long)bz * Astride);
    const uint2* B2 = (const uint2*)Bv + (BS ? (long)bz * Bstride : 0);
    const float* Bf = (const float*)Bv + (BS ? 0 : (long)bz * Bstride);
    uint2* C2 = (uint2*)Cv + (OS ? (long)bz * Cstride : 0);
    float* Cf = (float*)Cv + (OS ? 0 : (long)bz * Cstride);

    const int BK = 32;
    int tid  = threadIdx.x;
    int lane = tid & 31;
    int wid  = tid >> 5;
    int wm   = wid >> 2;
    int wn   = wid & 3;
    int g    = lane >> 2;
    int tg   = lane & 3;

    int row0 = blockIdx.y * 64;
    int col0 = xb * 64;

    unsigned asb = (unsigned)__cvta_generic_to_shared(smA);
    unsigned bsb = (unsigned)__cvta_generic_to_shared(smB);

    float c[2][2][4];
#pragma unroll
    for (int mi = 0; mi < 2; mi++)
#pragma unroll
        for (int ni = 0; ni < 2; ni++)
#pragma unroll
            for (int r = 0; r < 4; r++) c[mi][ni][r] = 0.f;

    int Keff  = band > 0 ? min(K, row0 + band) : K;
    int tiles = Keff / BK;
    int tA = (tiles * part) / SPLITK;
    int tB = (tiles * (part + 1)) / SPLITK;
    int T  = tB - tA;

    auto load_tile = [&](int tk, int st) {
        int k0 = tk * BK;
        unsigned ad = asb + st * SA;
        unsigned bd = bsb + st * SB;
        if (AS) {
#pragma unroll
            for (int i = 0; i < 4; i++) {
                int idx = tid + i * 256;
                int m = idx >> 4, kc = (idx & 15) << 1;
                CPA16(ad + (m * 34 + kc) * 8, &A2[(long)(row0 + m) * lda + k0 + kc]);
            }
        } else {
#pragma unroll
            for (int i = 0; i < 2; i++) {
                int idx = tid + i * 256;
                int m = idx >> 3, kc = (idx & 7) << 2;
                CPA16(ad + (m * 36 + kc) * 4, &Af[(long)(row0 + m) * lda + k0 + kc]);
            }
        }
        if (BT) {
            if (BS) {
#pragma unroll
                for (int i = 0; i < 4; i++) {
                    int idx = tid + i * 256;
                    int n = idx >> 4, kc = (idx & 15) << 1;
                    CPA16(bd + (n * 34 + kc) * 8, &B2[(long)(col0 + n) * ldb + k0 + kc]);
                }
            } else {
#pragma unroll
                for (int i = 0; i < 2; i++) {
                    int idx = tid + i * 256;
                    int n = idx >> 3, kc = (idx & 7) << 2;
                    CPA16(bd + (n * 36 + kc) * 4, &Bf[(long)(col0 + n) * ldb + k0 + kc]);
                }
            }
        } else {
            if (BS) {
#pragma unroll
                for (int i = 0; i < 4; i++) {
                    int idx = tid + i * 256;
                    int kk = idx >> 5, nc = (idx & 31) << 1;
                    CPA16(bd + (kk * 66 + nc) * 8, &B2[(long)(k0 + kk) * ldb + col0 + nc]);
                }
            } else {
#pragma unroll
                for (int i = 0; i < 2; i++) {
                    int idx = tid + i * 256;
                    int kk = idx >> 4, nc = (idx & 15) << 2;
                    CPA16(bd + (kk * 72 + nc) * 4, &Bf[(long)(k0 + kk) * ldb + col0 + nc]);
                }
            }
        }
        CPCOMMIT();
    };

    if (T > 0) load_tile(tA, 0);

    for (int t = 0; t < T; t++) {
        if (t + 1 < T) { load_tile(tA + t + 1, (t + 1) & 1); CPWAIT1(); }
        else           { CPWAIT0(); }
        __syncthreads();

        const uint2* as2 = (const uint2*)(smA + (t & 1) * SA);
        const float* asf = (const float*)(smA + (t & 1) * SA);
        const uint2* bs2 = (const uint2*)(smB + (t & 1) * SB);
        const float* bsf = (const float*)(smB + (t & 1) * SB);

#pragma unroll
        for (int ks = 0; ks < BK; ks += 8) {
            uint32_t ah[2][4], al[2][4];
#pragma unroll
            for (int mi = 0; mi < 2; mi++) {
                int mb = wm * 32 + mi * 16;
                if (AS) {
                    uint2 v0 = as2[(mb + g)     * 34 + ks + tg];
                    uint2 v1 = as2[(mb + g + 8) * 34 + ks + tg];
                    uint2 v2 = as2[(mb + g)     * 34 + ks + tg + 4];
                    uint2 v3 = as2[(mb + g + 8) * 34 + ks + tg + 4];
                    ah[mi][0] = v0.x; al[mi][0] = v0.y;
                    ah[mi][1] = v1.x; al[mi][1] = v1.y;
                    ah[mi][2] = v2.x; al[mi][2] = v2.y;
                    ah[mi][3] = v3.x; al[mi][3] = v3.y;
                } else {
                    split_tf32(asf[(mb + g)     * 36 + ks + tg],     ah[mi][0], al[mi][0]);
                    split_tf32(asf[(mb + g + 8) * 36 + ks + tg],     ah[mi][1], al[mi][1]);
                    split_tf32(asf[(mb + g)     * 36 + ks + tg + 4], ah[mi][2], al[mi][2]);
                    split_tf32(asf[(mb + g + 8) * 36 + ks + tg + 4], ah[mi][3], al[mi][3]);
                }
            }
            uint32_t bh[2][2], bl[2][2];
#pragma unroll
            for (int ni = 0; ni < 2; ni++) {
                int nb = wn * 16 + ni * 8 + g;
                if (BT) {
                    if (BS) {
                        uint2 w0 = bs2[nb * 34 + ks + tg];
                        uint2 w1 = bs2[nb * 34 + ks + tg + 4];
                        bh[ni][0] = w0.x; bl[ni][0] = w0.y;
                        bh[ni][1] = w1.x; bl[ni][1] = w1.y;
                    } else {
                        split_tf32(bsf[nb * 36 + ks + tg],     bh[ni][0], bl[ni][0]);
                        split_tf32(bsf[nb * 36 + ks + tg + 4], bh[ni][1], bl[ni][1]);
                    }
                } else {
                    if (BS) {
                        uint2 w0 = bs2[(ks + tg)     * 66 + nb];
                        uint2 w1 = bs2[(ks + tg + 4) * 66 + nb];
                        bh[ni][0] = w0.x; bl[ni][0] = w0.y;
                        bh[ni][1] = w1.x; bl[ni][1] = w1.y;
                    } else {
                        split_tf32(bsf[(ks + tg)     * 72 + nb], bh[ni][0], bl[ni][0]);
                        split_tf32(bsf[(ks + tg + 4) * 72 + nb], bh[ni][1], bl[ni][1]);
                    }
                }
            }
#pragma unroll
            for (int mi = 0; mi < 2; mi++)
#pragma unroll
                for (int ni = 0; ni < 2; ni++) {
                    mma8(c[mi][ni], ah[mi], bh[ni]);
                    mma8(c[mi][ni], ah[mi], bl[ni]);
                    mma8(c[mi][ni], al[mi], bh[ni]);
                }
        }
        __syncthreads();
    }

    // ---- epilogue ----
#pragma unroll
    for (int mi = 0; mi < 2; mi++) {
#pragma unroll
        for (int ni = 0; ni < 2; ni++) {
            int row = row0 + wm * 32 + mi * 16 + g;
            int col = col0 + wn * 16 + ni * 8 + 2 * tg;
            float v0 = c[mi][ni][0] * alpha;
            float v1 = c[mi][ni][1] * alpha;
            float v2 = c[mi][ni][2] * alpha;
            float v3 = c[mi][ni][3] * alpha;
            if (EPI == 3) {
                atomicAdd(&Cf[(long)row * ldc + col],           v0);
                atomicAdd(&Cf[(long)row * ldc + col + 1],       v1);
                atomicAdd(&Cf[(long)(row + 8) * ldc + col],     v2);
                atomicAdd(&Cf[(long)(row + 8) * ldc + col + 1], v3);
            } else {
                if (EPI >= 1) {
                    float b0 = bias[col], b1 = bias[col + 1];
                    v0 += b0; v1 += b1; v2 += b0; v3 += b1;
                }
                if (EPI == 2) {
                    v0 = 1.f / (1.f + expf(-v0));
                    v1 = 1.f / (1.f + expf(-v1));
                    v2 = 1.f / (1.f + expf(-v2));
                    v3 = 1.f / (1.f + expf(-v3));
                }
                if (OS) {
                    uint32_t h0, l0, h1, l1;
                    split_tf32(v0, h0, l0); split_tf32(v1, h1, l1);
                    *(uint4*)&C2[(long)row * ldc + col] = make_uint4(h0, l0, h1, l1);
                    split_tf32(v2, h0, l0); split_tf32(v3, h1, l1);
                    *(uint4*)&C2[(long)(row + 8) * ldc + col] = make_uint4(h0, l0, h1, l1);
                } else {
                    *(float2*)&Cf[(long)row * ldc + col]       = make_float2(v0, v1);
                    *(float2*)&Cf[(long)(row + 8) * ldc + col] = make_float2(v2, v3);
                }
            }
        }
    }
}

// ---------------------------------------------------------------------------
// SSM sequential scan. 16 lanes per channel; writes H pre-split (uint2).
// ---------------------------------------------------------------------------
__global__ __launch_bounds__(128)
void ssm_kernel(const float* __restrict__ x, const float* __restrict__ gate,
                const float* __restrict__ Amat, const float* __restrict__ Bm,
                const float* __restrict__ Cm, const float* __restrict__ log_dt,
                uint2* __restrict__ Hout)
{
    int lane = threadIdx.x & 15;
    int d = blockIdx.x * (blockDim.x >> 4) + (threadIdx.x >> 4);
    if (d >= D_DIM) return;

    float Arow[N_STATE];
#pragma unroll
    for (int m = 0; m < N_STATE; m++) Arow[m] = Amat[lane * N_STATE + m];
    float Bn  = Bm[lane * D_DIM + d];
    float Cn  = Cm[d * N_STATE + lane];
    float dtd = fminf(fmaxf(expf(log_dt[d]), 1e-3f), 1e-1f);

    float h  = 0.f;
    float xv = __ldg(&x[d]);
    float gv = __ldg(&gate[d]);

    for (int t = 0; t < S_LEN; t++) {
        float xn = 0.f, gn = 0.f;
        if (t + 1 < S_LEN) {
            xn = __ldg(&x[(t + 1) * D_DIM + d]);
            gn = __ldg(&gate[(t + 1) * D_DIM + d]);
        }
        float p0 = 0.f, p1 = 0.f, p2 = 0.f, p3 = 0.f;
#pragma unroll
        for (int m = 0; m < 4; m++) {
            p0 = fmaf(Arow[m],      __shfl_sync(FULLM, h, m,      16), p0);
            p1 = fmaf(Arow[m + 4],  __shfl_sync(FULLM, h, m + 4,  16), p1);
            p2 = fmaf(Arow[m + 8],  __shfl_sync(FULLM, h, m + 8,  16), p2);
            p3 = fmaf(Arow[m + 12], __shfl_sync(FULLM, h, m + 12, 16), p3);
        }
        float acc = (p0 + p1) + (p2 + p3);
        float sc  = (acc + xv * Bn) * dtd;
        float gm  = (fabsf(sc) > SPIKE) ? gv : 0.f;
        h = fmaf(sc, gm, h);

        float pr = h * Cn;
#pragma unroll
        for (int off = 8; off; off >>= 1)
            pr += __shfl_xor_sync(FULLM, pr, off, 16);
        if (lane == 0) {
            float val = xv + pr;
            uint32_t hi, lo;
            split_tf32(val, hi, lo);
            Hout[t * D_DIM + d] = make_uint2(hi, lo);
        }
        xv = xn; gv = gn;
    }
}

// ---------------------------------------------------------------------------
// Per-row: radix-select kk-th largest |score|, local+sparse mask, softmax.
// Row in registers; per-warp histograms; warp-0 shuffle suffix-scan.
// Writes only the banded region read by PV (j < (i&~63)+192).
// ---------------------------------------------------------------------------
__global__ __launch_bounds__(256)
void mask_softmax_kernel(float* __restrict__ scores)
{
    int i  = blockIdx.x;
    int hd = blockIdx.y;
    float* row = scores + ((size_t)hd * S_LEN + i) * S_LEN;

    __shared__ int   hist[8][256];
    __shared__ int   red[256];
    __shared__ int   sh_sel[2];
    __shared__ float fred[8];

    int tid = threadIdx.x, lane = tid & 31, wid = tid >> 5;

    float r[8]; unsigned u[8];
    {
        float4 v0 = *(const float4*)&row[tid * 8];
        float4 v1 = *(const float4*)&row[tid * 8 + 4];
        r[0] = v0.x; r[1] = v0.y; r[2] = v0.z; r[3] = v0.w;
        r[4] = v1.x; r[5] = v1.y; r[6] = v1.z; r[7] = v1.w;
    }
#pragma unroll
    for (int e = 0; e < 8; e++) u[e] = __float_as_uint(fabsf(r[e]));

    unsigned prefix = 0;
    int kneed = KK;
#pragma unroll
    for (int byte = 3; byte >= 0; --byte) {
        for (int b = lane; b < 256; b += 32) hist[wid][b] = 0;
        __syncthreads();
        unsigned pm = (byte == 3) ? 0u : (0xFFFFFFFFu << (8 * (byte + 1)));
#pragma unroll
        for (int e = 0; e < 8; e++)
            if ((u[e] & pm) == prefix)
                atomicAdd(&hist[wid][(u[e] >> (8 * byte)) & 255], 1);
        __syncthreads();
        int cnt = 0;
#pragma unroll
        for (int w = 0; w < 8; w++) cnt += hist[w][tid];
        red[tid] = cnt;
        __syncthreads();
        if (wid == 0) {
            int v[8], cum[8], s = 0;
#pragma unroll
            for (int e = 0; e < 8; e++) {
                v[e] = red[255 - (lane * 8 + e)];
                s += v[e];
                cum[e] = s;
            }
            int incl = s;
#pragma unroll
            for (int off = 1; off < 32; off <<= 1) {
                int t2 = __shfl_up_sync(FULLM, incl, off);
                if (lane >= off) incl += t2;
            }
            int excl = incl - s;
            bool has = (excl + cum[7]) >= kneed && excl < kneed;
            unsigned bal = __ballot_sync(FULLM, has);
            int fl = __ffs(bal) - 1;
            if (lane == fl) {
                int e = 0;
                while (excl + cum[e] < kneed) e++;
                sh_sel[0] = 255 - (lane * 8 + e);
                sh_sel[1] = kneed - (excl + cum[e] - v[e]);
            }
        }
        __syncthreads();
        prefix |= ((unsigned)sh_sel[0]) << (8 * byte);
        kneed = sh_sel[1];
        __syncthreads();
    }
    unsigned T = prefix;

    int jmax = i + WINDOW;
    float m = -INFINITY;
    float sv[8];
#pragma unroll
    for (int e = 0; e < 8; e++) {
        int j = tid * 8 + e;
        bool keep = (j <= jmax) && (u[e] >= T);
        sv[e] = keep ? r[e] : -INFINITY;
        m = fmaxf(m, sv[e]);
    }
#pragma unroll
    for (int off = 16; off; off >>= 1)
        m = fmaxf(m, __shfl_xor_sync(FULLM, m, off));
    if (lane == 0) fred[wid] = m;
    __syncthreads();
    float mm = -INFINITY;
#pragma unroll
    for (int w = 0; w < 8; w++) mm = fmaxf(mm, fred[w]);
    __syncthreads();

    float z = 0.f;
    float ex[8];
#pragma unroll
    for (int e = 0; e < 8; e++) {
        ex[e] = (sv[e] == -INFINITY) ? 0.f : __expf(sv[e] - mm);
        z += ex[e];
    }
#pragma unroll
    for (int off = 16; off; off >>= 1)
        z += __shfl_xor_sync(FULLM, z, off);
    if (lane == 0) fred[wid] = z;
    __syncthreads();
    float zz = 0.f;
#pragma unroll
    for (int w = 0; w < 8; w++) zz += fred[w];
    float inv = (zz > 0.f) ? 1.f / zz : 0.f;

    // PV (BM=64, band=192) only reads j < (i&~63)+192; rest stays unread.
    int limit = (i & ~63) + 192;
    if (tid * 8 < limit) {
        float4 o0 = make_float4(ex[0] * inv, ex[1] * inv, ex[2] * inv, ex[3] * inv);
        float4 o1 = make_float4(ex[4] * inv, ex[5] * inv, ex[6] * inv, ex[7] * inv);
        *(float4*)&row[tid * 8]     = o0;
        *(float4*)&row[tid * 8 + 4] = o1;
    }
}

// ---------------------------------------------------------------------------
// Launch
// ---------------------------------------------------------------------------
extern "C" void kernel_launch(void* const* d_in, const int* in_sizes, int n_in,
                              void* d_out, int out_size)
{
    const float* x      = (const float*)d_in[0];
    const float* Amat   = (const float*)d_in[1];
    const float* Bm     = (const float*)d_in[2];
    const float* Cm     = (const float*)d_in[3];
    const float* log_dt = (const float*)d_in[4];
    const float* Wg = (const float*)d_in[5];  const float* bg = (const float*)d_in[6];
    const float* Wq = (const float*)d_in[7];  const float* bq = (const float*)d_in[8];
    const float* Wk = (const float*)d_in[9];  const float* bk = (const float*)d_in[10];
    const float* Wv = (const float*)d_in[11]; const float* bv = (const float*)d_in[12];
    const float* Wd = (const float*)d_in[13]; const float* bd = (const float*)d_in[14];
    float* out = (float*)d_out;

    float *gate, *ctx, *scores;
    uint2 *xs, *Hs, *Qs, *Ks, *Vs, *Ws;
    cudaGetSymbolAddress((void**)&gate,   g_gate);
    cudaGetSymbolAddress((void**)&ctx,    g_ctx);
    cudaGetSymbolAddress((void**)&scores, g_scores);
    cudaGetSymbolAddress((void**)&xs,     g_xs);
    cudaGetSymbolAddress((void**)&Hs,     g_Hs);
    cudaGetSymbolAddress((void**)&Qs,     g_Qs);
    cudaGetSymbolAddress((void**)&Ks,     g_Ks);
    cudaGetSymbolAddress((void**)&Vs,     g_Vs);
    cudaGetSymbolAddress((void**)&Ws,     g_Ws);
    uint2* Wgs = Ws;
    uint2* Wqs = Ws + 1 * D_DIM * D_DIM;
    uint2* Wks = Ws + 2 * D_DIM * D_DIM;
    uint2* Wvs = Ws + 3 * D_DIM * D_DIM;
    uint2* Wds = Ws + 4 * D_DIM * D_DIM;

    // smem sizes per instantiation
    const int SM_GATE = GP<true,  true,  true,  false, 2, 1>::SMEM;
    const int SM_QKV  = GP<true,  true,  true,  true,  1, 1>::SMEM;
    const int SM_SC   = GP<true,  true,  true,  false, 0, 1>::SMEM;
    const int SM_PV   = GP<false, false, true,  false, 3, 2>::SMEM;
    const int SM_OUT  = GP<true,  false, true,  false, 1, 1>::SMEM;
    cudaFuncSetAttribute(gemm_tc<true,  true,  true,  false, 2, 1>,
        cudaFuncAttributeMaxDynamicSharedMemorySize, SM_GATE);
    cudaFuncSetAttribute(gemm_tc<true,  true,  true,  true,  1, 1>,
        cudaFuncAttributeMaxDynamicSharedMemorySize, SM_QKV);
    cudaFuncSetAttribute(gemm_tc<true,  true,  true,  false, 0, 1>,
        cudaFuncAttributeMaxDynamicSharedMemorySize, SM_SC);
    cudaFuncSetAttribute(gemm_tc<false, false, true,  false, 3, 2>,
        cudaFuncAttributeMaxDynamicSharedMemorySize, SM_PV);
    cudaFuncSetAttribute(gemm_tc<true,  false, true,  false, 1, 1>,
        cudaFuncAttributeMaxDynamicSharedMemorySize, SM_OUT);

    dim3 blk(256);

    // 0) pre-split x and all 5 weight matrices
    {
        dim3 grid((S_LEN * D_DIM) / 1024, 6);
        split6<<<grid, blk>>>(x, Wg, Wq, Wk, Wv, Wd, xs, Wgs, Wqs, Wks, Wvs, Wds);
    }
    // 1) gate = sigmoid(X Wg^T + bg)
    {
        dim3 grid(D_DIM / 64, S_LEN / 64, 1);
        gemm_tc<true, true, true, false, 2, 1><<<grid, blk, SM_GATE>>>(
            xs, Wgs, Wgs, Wgs, bg, bg, bg, gate, gate, gate,
            D_DIM, D_DIM, D_DIM, D_DIM, 0, 0, 0, 1.f, 0, D_DIM / 64);
    }
    // 2) SSM scan -> Hs (pre-split)
    ssm_kernel<<<D_DIM / 8, 128>>>(x, gate, Amat, Bm, Cm, log_dt, Hs);

    // 3) Fused Q,K,V projections -> pre-split outputs
    {
        dim3 grid(3 * D_DIM / 64, S_LEN / 64, 1);
        gemm_tc<true, true, true, true, 1, 1><<<grid, blk, SM_QKV>>>(
            Hs, Wqs, Wks, Wvs, bq, bk, bv, Qs, Ks, Vs,
            D_DIM, D_DIM, D_DIM, D_DIM, 0, 0, 0, 1.f, 0, D_DIM / 64);
    }
    // 4) scores[h] = Q_h K_h^T / 8  (pre-split operands, zero in-loop cvt)
    {
        dim3 grid(S_LEN / 64, S_LEN / 64, N_HEADS);
        gemm_tc<true, true, true, false, 0, 1><<<grid, blk, SM_SC>>>(
            Qs, Ks, Ks, Ks, nullptr, nullptr, nullptr, scores, scores, scores,
            DH, D_DIM, D_DIM, S_LEN, DH, DH, (long)S_LEN * S_LEN,
            0.125f, 0, S_LEN / 64);
    }
    // 5) per-row top-k select + masks + softmax (in place, banded writes)
    {
        dim3 grid(S_LEN, N_HEADS);
        mask_softmax_kernel<<<grid, blk>>>(scores);
    }
    // 6) ctx[h] = P_h V_h   (banded, split-K=2, atomic adds; V pre-split)
    {
        cudaMemsetAsync(ctx, 0, (size_t)S_LEN * D_DIM * sizeof(float));
        dim3 grid(DH / 64, S_LEN / 64, N_HEADS * 2);
        gemm_tc<false, false, true, false, 3, 2><<<grid, blk, SM_PV>>>(
            scores, Vs, Vs, Vs, nullptr, nullptr, nullptr, ctx, ctx, ctx,
            S_LEN, S_LEN, D_DIM, D_DIM, (long)S_LEN * S_LEN, DH, DH,
            1.f, 64 + WINDOW, DH / 64);
    }
    // 7) out = ctx Wd^T + bd
    {
        dim3 grid(D_DIM / 64, S_LEN / 64, 1);
        gemm_tc<true, false, true, false, 1, 1><<<grid, blk, SM_OUT>>>(
            ctx, Wds, Wds, Wds, bd, bd, bd, out, out, out,
            D_DIM, D_DIM, D_DIM, D_DIM, 0, 0, 0, 1.f, 0, D_DIM / 64);
    }
}

// round 12
// speedup vs baseline: 1.1407x; 1.1407x over previous
#include <cuda_runtime.h>
#include <cuda_bf16.h>
#include <math.h>
#include <stdint.h>

// Problem constants
#define S_LEN 2048
#define D_DIM 768
#define N_STATE 16
#define N_HEADS 12
#define DH 64
#define WINDOW 128
#define KK 1843            // int((1-0.1)*2048)
#define SPIKE 0.1f
#define FULLM 0xffffffffu

// ---------------------------------------------------------------------------
// Scratch (device globals; no dynamic allocation allowed)
// ---------------------------------------------------------------------------
__device__ float g_gate[S_LEN * D_DIM];
__device__ float g_H[S_LEN * D_DIM];
__device__ float g_Q[S_LEN * D_DIM];
__device__ float g_K[S_LEN * D_DIM];
__device__ float g_V[S_LEN * D_DIM];
__device__ float g_ctx[S_LEN * D_DIM];
__device__ float g_scores[(size_t)N_HEADS * S_LEN * S_LEN];   // 192 MB

// ---------------------------------------------------------------------------
// Split-TF32 helpers (3-MMA emulation of fp32 GEMM on tensor cores)
// ---------------------------------------------------------------------------
__device__ __forceinline__ void split_tf32(float a, uint32_t& hi, uint32_t& lo) {
    asm("cvt.rna.tf32.f32 %0, %1;" : "=r"(hi) : "f"(a));
    float r = a - __uint_as_float(hi);
    asm("cvt.rna.tf32.f32 %0, %1;" : "=r"(lo) : "f"(r));
}

__device__ __forceinline__ void mma8(float c[4], const uint32_t a[4], const uint32_t b[2]) {
    asm("mma.sync.aligned.m16n8k8.row.col.f32.tf32.tf32.f32 "
        "{%0,%1,%2,%3},{%4,%5,%6,%7},{%8,%9},{%0,%1,%2,%3};"
        : "+f"(c[0]), "+f"(c[1]), "+f"(c[2]), "+f"(c[3])
        : "r"(a[0]), "r"(a[1]), "r"(a[2]), "r"(a[3]), "r"(b[0]), "r"(b[1]));
}

#define CPA16(dst, src) asm volatile("cp.async.ca.shared.global [%0], [%1], 16;" :: "r"(dst), "l"(src))
#define CPCOMMIT()      asm volatile("cp.async.commit_group;" ::: "memory")
#define CPWAIT1()       asm volatile("cp.async.wait_group 1;" ::: "memory")
#define CPWAIT0()       asm volatile("cp.async.wait_group 0;" ::: "memory")

// ---------------------------------------------------------------------------
// Tensor-core GEMM (split tf32, 3-MMA).
//   BT=true : C[m,n] = alpha*sum_k A[m,k]*B[n,k];  BT=false: B[k,n]
//   BKT: k-tile (32 or 64). NS: pipeline stages (1 or 2).
//   EPI: 0 none, 1 +bias, 2 sigmoid(v+bias), 3 atomicAdd (split-K)
// Tiles BM=BN=64; 256 thr, 8 warps (2m x 4n), warp tile 32x16.
// B/bias/C selected by blockIdx.x / nper (fused QKV).
// band>0 limits k to row0+band; SPLITK parts via blockIdx.z.
// ---------------------------------------------------------------------------
template<int BKT, int NS, bool BT, int EPI, int SPLITK>
__global__ __launch_bounds__(256)
void gemm_tc(const float* __restrict__ A,
             const float* __restrict__ B0, const float* __restrict__ B1,
             const float* __restrict__ B2,
             const float* __restrict__ bi0, const float* __restrict__ bi1,
             const float* __restrict__ bi2,
             float* __restrict__ C0, float* __restrict__ C1, float* __restrict__ C2,
             int K, int lda, int ldb, int ldc,
             long Astride, long Bstride, long Cstride,
             float alpha, int band, int nper)
{
    const int LD  = BKT + 4;                 // padded A/B (BT) row stride
    const int ASZ = 64 * LD;                 // floats per A stage
    const int BSZ = BT ? 64 * LD : BKT * 72; // floats per B stage
    const int F4R = BKT / 4;                 // float4s per row
    const int SH  = (BKT == 32) ? 3 : 4;

    __shared__ float As[NS][ASZ];
    __shared__ float Bs[NS][BSZ];

    int bz   = blockIdx.z / SPLITK;
    int part = blockIdx.z % SPLITK;
    int sel  = blockIdx.x / nper;
    int xb   = blockIdx.x % nper;

    const float* B    = (sel == 0) ? B0  : (sel == 1) ? B1  : B2;
    const float* bias = (sel == 0) ? bi0 : (sel == 1) ? bi1 : bi2;
    float*       C    = (sel == 0) ? C0  : (sel == 1) ? C1  : C2;

    A += (long)bz * Astride;
    B += (long)bz * Bstride;
    C += (long)bz * Cstride;

    int tid  = threadIdx.x;
    int lane = tid & 31;
    int wid  = tid >> 5;
    int wm   = wid >> 2;
    int wn   = wid & 3;
    int g    = lane >> 2;
    int tg   = lane & 3;

    int row0 = blockIdx.y * 64;
    int col0 = xb * 64;

    unsigned asb = (unsigned)__cvta_generic_to_shared(&As[0][0]);
    unsigned bsb = (unsigned)__cvta_generic_to_shared(&Bs[0][0]);

    float c[2][2][4];
#pragma unroll
    for (int mi = 0; mi < 2; mi++)
#pragma unroll
        for (int ni = 0; ni < 2; ni++)
#pragma unroll
            for (int r = 0; r < 4; r++) c[mi][ni][r] = 0.f;

    int Keff  = band > 0 ? min(K, row0 + band) : K;
    int tiles = Keff / BKT;
    int tA = (tiles * part) / SPLITK;
    int tB = (tiles * (part + 1)) / SPLITK;
    int T  = tB - tA;

    auto load_tile = [&](int tk, int st) {
        int k0 = tk * BKT;
        unsigned ad = asb + st * ASZ * 4;
        unsigned bd = bsb + st * BSZ * 4;
#pragma unroll
        for (int i = 0; i < BKT / 16; i++) {
            int idx = tid + i * 256;
            int m = idx >> SH, kc = (idx & (F4R - 1)) << 2;
            CPA16(ad + (m * LD + kc) * 4, &A[(long)(row0 + m) * lda + k0 + kc]);
        }
        if (BT) {
#pragma unroll
            for (int i = 0; i < BKT / 16; i++) {
                int idx = tid + i * 256;
                int n = idx >> SH, kc = (idx & (F4R - 1)) << 2;
                CPA16(bd + (n * LD + kc) * 4, &B[(long)(col0 + n) * ldb + k0 + kc]);
            }
        } else {
#pragma unroll
            for (int i = 0; i < BKT / 16; i++) {
                int idx = tid + i * 256;
                int kk = idx >> 4, nc = (idx & 15) << 2;
                CPA16(bd + (kk * 72 + nc) * 4, &B[(long)(k0 + kk) * ldb + col0 + nc]);
            }
        }
        CPCOMMIT();
    };

    auto compute = [&](int st) {
        const float* as = As[st];
        const float* bs = Bs[st];
#pragma unroll
        for (int ks = 0; ks < BKT; ks += 8) {
            uint32_t ah[2][4], al[2][4];
#pragma unroll
            for (int mi = 0; mi < 2; mi++) {
                int mb = wm * 32 + mi * 16;
                split_tf32(as[(mb + g)     * LD + ks + tg],     ah[mi][0], al[mi][0]);
                split_tf32(as[(mb + g + 8) * LD + ks + tg],     ah[mi][1], al[mi][1]);
                split_tf32(as[(mb + g)     * LD + ks + tg + 4], ah[mi][2], al[mi][2]);
                split_tf32(as[(mb + g + 8) * LD + ks + tg + 4], ah[mi][3], al[mi][3]);
            }
            uint32_t bh[2][2], bl[2][2];
#pragma unroll
            for (int ni = 0; ni < 2; ni++) {
                int nb = wn * 16 + ni * 8 + g;
                float f0 = BT ? bs[nb * LD + ks + tg]     : bs[(ks + tg)     * 72 + nb];
                float f1 = BT ? bs[nb * LD + ks + tg + 4] : bs[(ks + tg + 4) * 72 + nb];
                split_tf32(f0, bh[ni][0], bl[ni][0]);
                split_tf32(f1, bh[ni][1], bl[ni][1]);
            }
#pragma unroll
            for (int mi = 0; mi < 2; mi++)
#pragma unroll
                for (int ni = 0; ni < 2; ni++) {
                    mma8(c[mi][ni], ah[mi], bh[ni]);
                    mma8(c[mi][ni], ah[mi], bl[ni]);
                    mma8(c[mi][ni], al[mi], bh[ni]);
                }
        }
    };

    if (NS == 1) {
        for (int t = 0; t < T; t++) {
            load_tile(tA + t, 0);
            CPWAIT0();
            __syncthreads();
            compute(0);
            __syncthreads();
        }
    } else {
        if (T > 0) load_tile(tA, 0);
        for (int t = 0; t < T; t++) {
            if (t + 1 < T) { load_tile(tA + t + 1, (t + 1) & 1); CPWAIT1(); }
            else           { CPWAIT0(); }
            __syncthreads();
            compute(t & 1);
            __syncthreads();
        }
    }

    // ---- epilogue ----
#pragma unroll
    for (int mi = 0; mi < 2; mi++) {
#pragma unroll
        for (int ni = 0; ni < 2; ni++) {
            int row = row0 + wm * 32 + mi * 16 + g;
            int col = col0 + wn * 16 + ni * 8 + 2 * tg;
            float v0 = c[mi][ni][0] * alpha;
            float v1 = c[mi][ni][1] * alpha;
            float v2 = c[mi][ni][2] * alpha;
            float v3 = c[mi][ni][3] * alpha;
            if (EPI == 3) {
                atomicAdd(&C[(long)row * ldc + col],           v0);
                atomicAdd(&C[(long)row * ldc + col + 1],       v1);
                atomicAdd(&C[(long)(row + 8) * ldc + col],     v2);
                atomicAdd(&C[(long)(row + 8) * ldc + col + 1], v3);
            } else {
                if (EPI >= 1) {
                    float b0 = bias[col], b1 = bias[col + 1];
                    v0 += b0; v1 += b1; v2 += b0; v3 += b1;
                }
                if (EPI == 2) {
                    v0 = 1.f / (1.f + expf(-v0));
                    v1 = 1.f / (1.f + expf(-v1));
                    v2 = 1.f / (1.f + expf(-v2));
                    v3 = 1.f / (1.f + expf(-v3));
                }
                *(float2*)&C[(long)row * ldc + col]       = make_float2(v0, v1);
                *(float2*)&C[(long)(row + 8) * ldc + col] = make_float2(v2, v3);
            }
        }
    }
}

// ---------------------------------------------------------------------------
// SSM sequential scan. 16 lanes per channel (lane = state index n).
// ---------------------------------------------------------------------------
__global__ __launch_bounds__(128)
void ssm_kernel(const float* __restrict__ x, const float* __restrict__ gate,
                const float* __restrict__ Amat, const float* __restrict__ Bm,
                const float* __restrict__ Cm, const float* __restrict__ log_dt,
                float* __restrict__ Hout)
{
    int lane = threadIdx.x & 15;
    int d = blockIdx.x * (blockDim.x >> 4) + (threadIdx.x >> 4);
    if (d >= D_DIM) return;

    float Arow[N_STATE];
#pragma unroll
    for (int m = 0; m < N_STATE; m++) Arow[m] = Amat[lane * N_STATE + m];
    float Bn  = Bm[lane * D_DIM + d];
    float Cn  = Cm[d * N_STATE + lane];
    float dtd = fminf(fmaxf(expf(log_dt[d]), 1e-3f), 1e-1f);

    float h  = 0.f;
    float xv = __ldg(&x[d]);
    float gv = __ldg(&gate[d]);

    for (int t = 0; t < S_LEN; t++) {
        float xn = 0.f, gn = 0.f;
        if (t + 1 < S_LEN) {
            xn = __ldg(&x[(t + 1) * D_DIM + d]);
            gn = __ldg(&gate[(t + 1) * D_DIM + d]);
        }
        float p0 = 0.f, p1 = 0.f, p2 = 0.f, p3 = 0.f;
#pragma unroll
        for (int m = 0; m < 4; m++) {
            p0 = fmaf(Arow[m],      __shfl_sync(FULLM, h, m,      16), p0);
            p1 = fmaf(Arow[m + 4],  __shfl_sync(FULLM, h, m + 4,  16), p1);
            p2 = fmaf(Arow[m + 8],  __shfl_sync(FULLM, h, m + 8,  16), p2);
            p3 = fmaf(Arow[m + 12], __shfl_sync(FULLM, h, m + 12, 16), p3);
        }
        float acc = (p0 + p1) + (p2 + p3);
        float sc  = (acc + xv * Bn) * dtd;
        float gm  = (fabsf(sc) > SPIKE) ? gv : 0.f;
        h = fmaf(sc, gm, h);

        float pr = h * Cn;
#pragma unroll
        for (int off = 8; off; off >>= 1)
            pr += __shfl_xor_sync(FULLM, pr, off, 16);
        if (lane == 0) Hout[t * D_DIM + d] = xv + pr;

        xv = xn; gv = gn;
    }
}

// ---------------------------------------------------------------------------
// Per-row: radix-select kk-th largest |score|, local+sparse mask, softmax.
// Row in registers; per-warp histograms with __match_any aggregation
// (1 atomic per same-bin group instead of 32-way serialization).
// Writes only the banded region read by PV (j < (i&~63)+192).
// ---------------------------------------------------------------------------
__global__ __launch_bounds__(256)
void mask_softmax_kernel(float* __restrict__ scores)
{
    int i  = blockIdx.x;
    int hd = blockIdx.y;
    float* row = scores + ((size_t)hd * S_LEN + i) * S_LEN;

    __shared__ int   hist[8][256];
    __shared__ int   red[256];
    __shared__ int   sh_sel[2];
    __shared__ float fred[8];

    int tid = threadIdx.x, lane = tid & 31, wid = tid >> 5;

    float r[8]; unsigned u[8];
    {
        float4 v0 = *(const float4*)&row[tid * 8];
        float4 v1 = *(const float4*)&row[tid * 8 + 4];
        r[0] = v0.x; r[1] = v0.y; r[2] = v0.z; r[3] = v0.w;
        r[4] = v1.x; r[5] = v1.y; r[6] = v1.z; r[7] = v1.w;
    }
#pragma unroll
    for (int e = 0; e < 8; e++) u[e] = __float_as_uint(fabsf(r[e]));

    unsigned prefix = 0;
    int kneed = KK;
#pragma unroll
    for (int byte = 3; byte >= 0; --byte) {
        for (int b = lane; b < 256; b += 32) hist[wid][b] = 0;
        __syncthreads();
        unsigned pm = (byte == 3) ? 0u : (0xFFFFFFFFu << (8 * (byte + 1)));
#pragma unroll
        for (int e = 0; e < 8; e++) {
            bool ok = (u[e] & pm) == prefix;
            unsigned bin = (u[e] >> (8 * byte)) & 255;
            unsigned key = ok ? bin : 0xFFFFFFFFu;
            unsigned grp = __match_any_sync(FULLM, key);
            int leader = __ffs(grp) - 1;
            if (ok && lane == leader)
                atomicAdd(&hist[wid][bin], __popc(grp));
        }
        __syncthreads();
        int cnt = 0;
#pragma unroll
        for (int w = 0; w < 8; w++) cnt += hist[w][tid];
        red[tid] = cnt;
        __syncthreads();
        if (wid == 0) {
            int v[8], cum[8], s = 0;
#pragma unroll
            for (int e = 0; e < 8; e++) {
                v[e] = red[255 - (lane * 8 + e)];
                s += v[e];
                cum[e] = s;
            }
            int incl = s;
#pragma unroll
            for (int off = 1; off < 32; off <<= 1) {
                int t2 = __shfl_up_sync(FULLM, incl, off);
                if (lane >= off) incl += t2;
            }
            int excl = incl - s;
            bool has = (excl + cum[7]) >= kneed && excl < kneed;
            unsigned bal = __ballot_sync(FULLM, has);
            int fl = __ffs(bal) - 1;
            if (lane == fl) {
                int e = 0;
                while (excl + cum[e] < kneed) e++;
                sh_sel[0] = 255 - (lane * 8 + e);
                sh_sel[1] = kneed - (excl + cum[e] - v[e]);
            }
        }
        __syncthreads();
        prefix |= ((unsigned)sh_sel[0]) << (8 * byte);
        kneed = sh_sel[1];
        __syncthreads();
    }
    unsigned T = prefix;

    int jmax = i + WINDOW;
    float m = -INFINITY;
    float sv[8];
#pragma unroll
    for (int e = 0; e < 8; e++) {
        int j = tid * 8 + e;
        bool keep = (j <= jmax) && (u[e] >= T);
        sv[e] = keep ? r[e] : -INFINITY;
        m = fmaxf(m, sv[e]);
    }
#pragma unroll
    for (int off = 16; off; off >>= 1)
        m = fmaxf(m, __shfl_xor_sync(FULLM, m, off));
    if (lane == 0) fred[wid] = m;
    __syncthreads();
    float mm = -INFINITY;
#pragma unroll
    for (int w = 0; w < 8; w++) mm = fmaxf(mm, fred[w]);
    __syncthreads();

    float z = 0.f;
    float ex[8];
#pragma unroll
    for (int e = 0; e < 8; e++) {
        ex[e] = (sv[e] == -INFINITY) ? 0.f : __expf(sv[e] - mm);
        z += ex[e];
    }
#pragma unroll
    for (int off = 16; off; off >>= 1)
        z += __shfl_xor_sync(FULLM, z, off);
    if (lane == 0) fred[wid] = z;
    __syncthreads();
    float zz = 0.f;
#pragma unroll
    for (int w = 0; w < 8; w++) zz += fred[w];
    float inv = (zz > 0.f) ? 1.f / zz : 0.f;

    // PV (BM=64, band=192) only reads j < (i&~63)+192; rest stays unread.
    int limit = (i & ~63) + 192;
    if (tid * 8 < limit) {
        float4 o0 = make_float4(ex[0] * inv, ex[1] * inv, ex[2] * inv, ex[3] * inv);
        float4 o1 = make_float4(ex[4] * inv, ex[5] * inv, ex[6] * inv, ex[7] * inv);
        *(float4*)&row[tid * 8]     = o0;
        *(float4*)&row[tid * 8 + 4] = o1;
    }
}

// ---------------------------------------------------------------------------
// Launch
// ---------------------------------------------------------------------------
extern "C" void kernel_launch(void* const* d_in, const int* in_sizes, int n_in,
                              void* d_out, int out_size)
{
    const float* x      = (const float*)d_in[0];
    const float* Amat   = (const float*)d_in[1];
    const float* Bm     = (const float*)d_in[2];
    const float* Cm     = (const float*)d_in[3];
    const float* log_dt = (const float*)d_in[4];
    const float* Wg = (const float*)d_in[5];  const float* bg = (const float*)d_in[6];
    const float* Wq = (const float*)d_in[7];  const float* bq = (const float*)d_in[8];
    const float* Wk = (const float*)d_in[9];  const float* bk = (const float*)d_in[10];
    const float* Wv = (const float*)d_in[11]; const float* bv = (const float*)d_in[12];
    const float* Wd = (const float*)d_in[13]; const float* bd = (const float*)d_in[14];
    float* out = (float*)d_out;

    float *gate, *H, *Q, *K, *V, *ctx, *scores;
    cudaGetSymbolAddress((void**)&gate,   g_gate);
    cudaGetSymbolAddress((void**)&H,      g_H);
    cudaGetSymbolAddress((void**)&Q,      g_Q);
    cudaGetSymbolAddress((void**)&K,      g_K);
    cudaGetSymbolAddress((void**)&V,      g_V);
    cudaGetSymbolAddress((void**)&ctx,    g_ctx);
    cudaGetSymbolAddress((void**)&scores, g_scores);

    dim3 blk(256);

    // 1) gate = sigmoid(X Wg^T + bg)
    {
        dim3 grid(D_DIM / 64, S_LEN / 64, 1);
        gemm_tc<32, 2, true, 2, 1><<<grid, blk>>>(x, Wg, Wg, Wg, bg, bg, bg,
            gate, gate, gate,
            D_DIM, D_DIM, D_DIM, D_DIM, 0, 0, 0, 1.f, 0, D_DIM / 64);
    }
    // 2) SSM scan -> H = x + y
    ssm_kernel<<<D_DIM / 8, 128>>>(x, gate, Amat, Bm, Cm, log_dt, H);

    // 3) Fused Q,K,V projections (B/C selected per x-block)
    {
        dim3 grid(3 * D_DIM / 64, S_LEN / 64, 1);
        gemm_tc<32, 2, true, 1, 1><<<grid, blk>>>(H, Wq, Wk, Wv, bq, bk, bv,
            Q, K, V,
            D_DIM, D_DIM, D_DIM, D_DIM, 0, 0, 0, 1.f, 0, D_DIM / 64);
    }
    // 4) scores[h] = Q_h K_h^T / 8   (K=64: one BK=64 tile, single stage)
    {
        dim3 grid(S_LEN / 64, S_LEN / 64, N_HEADS);
        gemm_tc<64, 1, true, 0, 1><<<grid, blk>>>(Q, K, K, K,
            nullptr, nullptr, nullptr, scores, scores, scores,
            DH, D_DIM, D_DIM, S_LEN,
            DH, DH, (long)S_LEN * S_LEN, 0.125f, 0, S_LEN / 64);
    }
    // 5) per-row top-k select + masks + softmax (in place, banded writes)
    {
        dim3 grid(S_LEN, N_HEADS);
        mask_softmax_kernel<<<grid, blk>>>(scores);
    }
    // 6) ctx[h] = P_h V_h   (banded, split-K=2, atomic adds)
    {
        cudaMemsetAsync(ctx, 0, (size_t)S_LEN * D_DIM * sizeof(float));
        dim3 grid(DH / 64, S_LEN / 64, N_HEADS * 2);
        gemm_tc<32, 2, false, 3, 2><<<grid, blk>>>(scores, V, V, V,
            nullptr, nullptr, nullptr, ctx, ctx, ctx,
            S_LEN, S_LEN, D_DIM, D_DIM,
            (long)S_LEN * S_LEN, DH, DH, 1.f, 64 + WINDOW, DH / 64);
    }
    // 7) out = ctx Wd^T + bd
    {
        dim3 grid(D_DIM / 64, S_LEN / 64, 1);
        gemm_tc<32, 2, true, 1, 1><<<grid, blk>>>(ctx, Wd, Wd, Wd, bd, bd, bd,
            out, out, out,
            D_DIM, D_DIM, D_DIM, D_DIM, 0, 0, 0, 1.f, 0, D_DIM / 64);
    }
}

// round 13
// speedup vs baseline: 1.2472x; 1.0933x over previous
#include <cuda_runtime.h>
#include <cuda_bf16.h>
#include <math.h>
#include <stdint.h>

// Problem constants
#define S_LEN 2048
#define D_DIM 768
#define N_STATE 16
#define N_HEADS 12
#define DH 64
#define WINDOW 128
#define KK 1843            // int((1-0.1)*2048)
#define SPIKE 0.1f
#define FULLM 0xffffffffu

// ---------------------------------------------------------------------------
// Scratch (device globals; no dynamic allocation allowed)
// ---------------------------------------------------------------------------
__device__ float g_gate[S_LEN * D_DIM];
__device__ float g_H[S_LEN * D_DIM];
__device__ float g_Q[S_LEN * D_DIM];
__device__ float g_K[S_LEN * D_DIM];
__device__ float g_V[S_LEN * D_DIM];
__device__ float g_ctx[S_LEN * D_DIM];
__device__ float g_scores[(size_t)N_HEADS * S_LEN * S_LEN];   // 192 MB

// ---------------------------------------------------------------------------
// Split-TF32 helpers (3-MMA emulation of fp32 GEMM on tensor cores)
// ---------------------------------------------------------------------------
__device__ __forceinline__ void split_tf32(float a, uint32_t& hi, uint32_t& lo) {
    asm("cvt.rna.tf32.f32 %0, %1;" : "=r"(hi) : "f"(a));
    float r = a - __uint_as_float(hi);
    asm("cvt.rna.tf32.f32 %0, %1;" : "=r"(lo) : "f"(r));
}

__device__ __forceinline__ void mma8(float c[4], const uint32_t a[4], const uint32_t b[2]) {
    asm("mma.sync.aligned.m16n8k8.row.col.f32.tf32.tf32.f32 "
        "{%0,%1,%2,%3},{%4,%5,%6,%7},{%8,%9},{%0,%1,%2,%3};"
        : "+f"(c[0]), "+f"(c[1]), "+f"(c[2]), "+f"(c[3])
        : "r"(a[0]), "r"(a[1]), "r"(a[2]), "r"(a[3]), "r"(b[0]), "r"(b[1]));
}

#define CPA16(dst, src) asm volatile("cp.async.ca.shared.global [%0], [%1], 16;" :: "r"(dst), "l"(src))
#define CPCOMMIT()      asm volatile("cp.async.commit_group;" ::: "memory")
#define CPWAIT1()       asm volatile("cp.async.wait_group 1;" ::: "memory")
#define CPWAIT0()       asm volatile("cp.async.wait_group 0;" ::: "memory")

// ---------------------------------------------------------------------------
// BM=64 GEMM (split tf32, 3-MMA). Used for scores (BT) and PV (!BT, banded).
//   BT=true : C[m,n] = alpha*sum_k A[m,k]*B[n,k];  BT=false: B[k,n]
// EPI: 0 none, 3 atomicAdd (split-K). BK=32, 2-stage cp.async.
// ---------------------------------------------------------------------------
template<bool BT, int EPI, int SPLITK>
__global__ __launch_bounds__(256)
void gemm_tc(const float* __restrict__ A, const float* __restrict__ B,
             float* __restrict__ C,
             int K, int lda, int ldb, int ldc,
             long Astride, long Bstride, long Cstride,
             float alpha, int band)
{
    const int BK = 32;
    __shared__ float As[2][64 * 36];
    __shared__ float Bs[2][64 * 36];

    int bz   = blockIdx.z / SPLITK;
    int part = blockIdx.z % SPLITK;
    A += (long)bz * Astride;
    B += (long)bz * Bstride;
    C += (long)bz * Cstride;

    int tid  = threadIdx.x;
    int lane = tid & 31;
    int wid  = tid >> 5;
    int wm   = wid >> 2;
    int wn   = wid & 3;
    int g    = lane >> 2;
    int tg   = lane & 3;

    int row0 = blockIdx.y * 64;
    int col0 = blockIdx.x * 64;

    unsigned asb = (unsigned)__cvta_generic_to_shared(&As[0][0]);
    unsigned bsb = (unsigned)__cvta_generic_to_shared(&Bs[0][0]);

    float c[2][2][4];
#pragma unroll
    for (int mi = 0; mi < 2; mi++)
#pragma unroll
        for (int ni = 0; ni < 2; ni++)
#pragma unroll
            for (int r = 0; r < 4; r++) c[mi][ni][r] = 0.f;

    int Keff  = band > 0 ? min(K, row0 + band) : K;
    int tiles = Keff / BK;
    int tA = (tiles * part) / SPLITK;
    int tB = (tiles * (part + 1)) / SPLITK;
    int T  = tB - tA;

    auto load_tile = [&](int tk, int st) {
        int k0 = tk * BK;
        unsigned ad = asb + st * (64 * 36 * 4);
        unsigned bd = bsb + st * (64 * 36 * 4);
#pragma unroll
        for (int i = 0; i < 2; i++) {
            int idx = tid + i * 256;
            int m = idx >> 3, kc = (idx & 7) << 2;
            CPA16(ad + (m * 36 + kc) * 4, &A[(long)(row0 + m) * lda + k0 + kc]);
        }
        if (BT) {
#pragma unroll
            for (int i = 0; i < 2; i++) {
                int idx = tid + i * 256;
                int n = idx >> 3, kc = (idx & 7) << 2;
                CPA16(bd + (n * 36 + kc) * 4, &B[(long)(col0 + n) * ldb + k0 + kc]);
            }
        } else {
#pragma unroll
            for (int i = 0; i < 2; i++) {
                int idx = tid + i * 256;
                int kk = idx >> 4, nc = (idx & 15) << 2;
                CPA16(bd + (kk * 72 + nc) * 4, &B[(long)(k0 + kk) * ldb + col0 + nc]);
            }
        }
        CPCOMMIT();
    };

    if (T > 0) load_tile(tA, 0);

    for (int t = 0; t < T; t++) {
        if (t + 1 < T) { load_tile(tA + t + 1, (t + 1) & 1); CPWAIT1(); }
        else           { CPWAIT0(); }
        __syncthreads();

        const float* as = As[t & 1];
        const float* bs = Bs[t & 1];
#pragma unroll
        for (int ks = 0; ks < BK; ks += 8) {
            uint32_t ah[2][4], al[2][4];
#pragma unroll
            for (int mi = 0; mi < 2; mi++) {
                int mb = wm * 32 + mi * 16;
                split_tf32(as[(mb + g)     * 36 + ks + tg],     ah[mi][0], al[mi][0]);
                split_tf32(as[(mb + g + 8) * 36 + ks + tg],     ah[mi][1], al[mi][1]);
                split_tf32(as[(mb + g)     * 36 + ks + tg + 4], ah[mi][2], al[mi][2]);
                split_tf32(as[(mb + g + 8) * 36 + ks + tg + 4], ah[mi][3], al[mi][3]);
            }
            uint32_t bh[2][2], bl[2][2];
#pragma unroll
            for (int ni = 0; ni < 2; ni++) {
                int nb = wn * 16 + ni * 8 + g;
                float f0 = BT ? bs[nb * 36 + ks + tg]     : bs[(ks + tg)     * 72 + nb];
                float f1 = BT ? bs[nb * 36 + ks + tg + 4] : bs[(ks + tg + 4) * 72 + nb];
                split_tf32(f0, bh[ni][0], bl[ni][0]);
                split_tf32(f1, bh[ni][1], bl[ni][1]);
            }
#pragma unroll
            for (int mi = 0; mi < 2; mi++)
#pragma unroll
                for (int ni = 0; ni < 2; ni++) {
                    mma8(c[mi][ni], ah[mi], bh[ni]);
                    mma8(c[mi][ni], ah[mi], bl[ni]);
                    mma8(c[mi][ni], al[mi], bh[ni]);
                }
        }
        __syncthreads();
    }

#pragma unroll
    for (int mi = 0; mi < 2; mi++) {
#pragma unroll
        for (int ni = 0; ni < 2; ni++) {
            int row = row0 + wm * 32 + mi * 16 + g;
            int col = col0 + wn * 16 + ni * 8 + 2 * tg;
            float v0 = c[mi][ni][0] * alpha;
            float v1 = c[mi][ni][1] * alpha;
            float v2 = c[mi][ni][2] * alpha;
            float v3 = c[mi][ni][3] * alpha;
            if (EPI == 3) {
                atomicAdd(&C[(long)row * ldc + col],           v0);
                atomicAdd(&C[(long)row * ldc + col + 1],       v1);
                atomicAdd(&C[(long)(row + 8) * ldc + col],     v2);
                atomicAdd(&C[(long)(row + 8) * ldc + col + 1], v3);
            } else {
                *(float2*)&C[(long)row * ldc + col]       = make_float2(v0, v1);
                *(float2*)&C[(long)(row + 8) * ldc + col] = make_float2(v2, v3);
            }
        }
    }
}

// ---------------------------------------------------------------------------
// BM=128 x BN=64 projection GEMM (split tf32, 3-MMA), BT only:
//   C[m,n] = sum_k A[m,k]*B[n,k] (+bias) (+sigmoid)
// 2-stage cp.async, dynamic smem (55.3 KB). 8 warps 4m x 2n, 32x32/warp.
// B/bias/C selected by blockIdx.x / nper (fused QKV).
// ---------------------------------------------------------------------------
#define SM128 (2 * (128 * 36 + 64 * 36) * 4)

template<int EPI>
__global__ __launch_bounds__(256)
void gemm_tc128(const float* __restrict__ A,
                const float* __restrict__ B0, const float* __restrict__ B1,
                const float* __restrict__ B2,
                const float* __restrict__ bi0, const float* __restrict__ bi1,
                const float* __restrict__ bi2,
                float* __restrict__ C0, float* __restrict__ C1, float* __restrict__ C2,
                int K, int lda, int ldb, int ldc, int nper)
{
    extern __shared__ float sm[];
    float* As = sm;                    // 2 stages x 128*36
    float* Bs = sm + 2 * 128 * 36;     // 2 stages x 64*36

    int sel = blockIdx.x / nper;
    int xb  = blockIdx.x % nper;
    const float* B    = (sel == 0) ? B0  : (sel == 1) ? B1  : B2;
    const float* bias = (sel == 0) ? bi0 : (sel == 1) ? bi1 : bi2;
    float*       C    = (sel == 0) ? C0  : (sel == 1) ? C1  : C2;

    const int BK = 32;
    int tid  = threadIdx.x;
    int lane = tid & 31;
    int wid  = tid >> 5;
    int wm   = wid >> 1;              // 0..3
    int wn   = wid & 1;               // 0..1
    int g    = lane >> 2;
    int tg   = lane & 3;

    int row0 = blockIdx.y * 128;
    int col0 = xb * 64;

    unsigned asb = (unsigned)__cvta_generic_to_shared(As);
    unsigned bsb = (unsigned)__cvta_generic_to_shared(Bs);

    float c[2][4][4];
#pragma unroll
    for (int mi = 0; mi < 2; mi++)
#pragma unroll
        for (int ni = 0; ni < 4; ni++)
#pragma unroll
            for (int r = 0; r < 4; r++) c[mi][ni][r] = 0.f;

    int T = K / BK;

    auto load_tile = [&](int tk, int st) {
        int k0 = tk * BK;
        unsigned ad = asb + st * (128 * 36 * 4);
        unsigned bd = bsb + st * (64 * 36 * 4);
#pragma unroll
        for (int i = 0; i < 4; i++) {
            int idx = tid + i * 256;           // 1024 float4
            int m = idx >> 3, kc = (idx & 7) << 2;
            CPA16(ad + (m * 36 + kc) * 4, &A[(long)(row0 + m) * lda + k0 + kc]);
        }
#pragma unroll
        for (int i = 0; i < 2; i++) {
            int idx = tid + i * 256;           // 512 float4
            int n = idx >> 3, kc = (idx & 7) << 2;
            CPA16(bd + (n * 36 + kc) * 4, &B[(long)(col0 + n) * ldb + k0 + kc]);
        }
        CPCOMMIT();
    };

    load_tile(0, 0);

    for (int t = 0; t < T; t++) {
        if (t + 1 < T) { load_tile(t + 1, (t + 1) & 1); CPWAIT1(); }
        else           { CPWAIT0(); }
        __syncthreads();

        const float* as = As + (t & 1) * 128 * 36;
        const float* bs = Bs + (t & 1) * 64 * 36;
#pragma unroll
        for (int ks = 0; ks < BK; ks += 8) {
            uint32_t ah[2][4], al[2][4];
#pragma unroll
            for (int mi = 0; mi < 2; mi++) {
                int mb = wm * 32 + mi * 16;
                split_tf32(as[(mb + g)     * 36 + ks + tg],     ah[mi][0], al[mi][0]);
                split_tf32(as[(mb + g + 8) * 36 + ks + tg],     ah[mi][1], al[mi][1]);
                split_tf32(as[(mb + g)     * 36 + ks + tg + 4], ah[mi][2], al[mi][2]);
                split_tf32(as[(mb + g + 8) * 36 + ks + tg + 4], ah[mi][3], al[mi][3]);
            }
            uint32_t bh[4][2], bl[4][2];
#pragma unroll
            for (int ni = 0; ni < 4; ni++) {
                int nb = wn * 32 + ni * 8 + g;
                split_tf32(bs[nb * 36 + ks + tg],     bh[ni][0], bl[ni][0]);
                split_tf32(bs[nb * 36 + ks + tg + 4], bh[ni][1], bl[ni][1]);
            }
#pragma unroll
            for (int mi = 0; mi < 2; mi++)
#pragma unroll
                for (int ni = 0; ni < 4; ni++) {
                    mma8(c[mi][ni], ah[mi], bh[ni]);
                    mma8(c[mi][ni], ah[mi], bl[ni]);
                    mma8(c[mi][ni], al[mi], bh[ni]);
                }
        }
        __syncthreads();
    }

#pragma unroll
    for (int mi = 0; mi < 2; mi++) {
#pragma unroll
        for (int ni = 0; ni < 4; ni++) {
            int row = row0 + wm * 32 + mi * 16 + g;
            int col = col0 + wn * 32 + ni * 8 + 2 * tg;
            float v0 = c[mi][ni][0];
            float v1 = c[mi][ni][1];
            float v2 = c[mi][ni][2];
            float v3 = c[mi][ni][3];
            if (EPI >= 1) {
                float b0 = bias[col], b1 = bias[col + 1];
                v0 += b0; v1 += b1; v2 += b0; v3 += b1;
            }
            if (EPI == 2) {
                v0 = 1.f / (1.f + expf(-v0));
                v1 = 1.f / (1.f + expf(-v1));
                v2 = 1.f / (1.f + expf(-v2));
                v3 = 1.f / (1.f + expf(-v3));
            }
            *(float2*)&C[(long)row * ldc + col]       = make_float2(v0, v1);
            *(float2*)&C[(long)(row + 8) * ldc + col] = make_float2(v2, v3);
        }
    }
}

// ---------------------------------------------------------------------------
// SSM sequential scan. 16 lanes per channel (lane = state index n).
// ---------------------------------------------------------------------------
__global__ __launch_bounds__(128)
void ssm_kernel(const float* __restrict__ x, const float* __restrict__ gate,
                const float* __restrict__ Amat, const float* __restrict__ Bm,
                const float* __restrict__ Cm, const float* __restrict__ log_dt,
                float* __restrict__ Hout)
{
    int lane = threadIdx.x & 15;
    int d = blockIdx.x * (blockDim.x >> 4) + (threadIdx.x >> 4);
    if (d >= D_DIM) return;

    float Arow[N_STATE];
#pragma unroll
    for (int m = 0; m < N_STATE; m++) Arow[m] = Amat[lane * N_STATE + m];
    float Bn  = Bm[lane * D_DIM + d];
    float Cn  = Cm[d * N_STATE + lane];
    float dtd = fminf(fmaxf(expf(log_dt[d]), 1e-3f), 1e-1f);

    float h  = 0.f;
    float xv = __ldg(&x[d]);
    float gv = __ldg(&gate[d]);

    for (int t = 0; t < S_LEN; t++) {
        float xn = 0.f, gn = 0.f;
        if (t + 1 < S_LEN) {
            xn = __ldg(&x[(t + 1) * D_DIM + d]);
            gn = __ldg(&gate[(t + 1) * D_DIM + d]);
        }
        float p0 = 0.f, p1 = 0.f, p2 = 0.f, p3 = 0.f;
#pragma unroll
        for (int m = 0; m < 4; m++) {
            p0 = fmaf(Arow[m],      __shfl_sync(FULLM, h, m,      16), p0);
            p1 = fmaf(Arow[m + 4],  __shfl_sync(FULLM, h, m + 4,  16), p1);
            p2 = fmaf(Arow[m + 8],  __shfl_sync(FULLM, h, m + 8,  16), p2);
            p3 = fmaf(Arow[m + 12], __shfl_sync(FULLM, h, m + 12, 16), p3);
        }
        float acc = (p0 + p1) + (p2 + p3);
        float sc  = (acc + xv * Bn) * dtd;
        float gm  = (fabsf(sc) > SPIKE) ? gv : 0.f;
        h = fmaf(sc, gm, h);

        float pr = h * Cn;
#pragma unroll
        for (int off = 8; off; off >>= 1)
            pr += __shfl_xor_sync(FULLM, pr, off, 16);
        if (lane == 0) Hout[t * D_DIM + d] = xv + pr;

        xv = xn; gv = gn;
    }
}

// ---------------------------------------------------------------------------
// Per-row: radix-select kk-th largest |score|, local+sparse mask, softmax.
// Row in registers; per-warp histograms (plain atomics — HW aggregates
// same-address smem atomics at 32cyc/warp); warp-0 shuffle suffix-scan.
// Writes only the banded region read by PV (j < (i&~63)+192).
// ---------------------------------------------------------------------------
__global__ __launch_bounds__(256)
void mask_softmax_kernel(float* __restrict__ scores)
{
    int i  = blockIdx.x;
    int hd = blockIdx.y;
    float* row = scores + ((size_t)hd * S_LEN + i) * S_LEN;

    __shared__ int   hist[8][256];
    __shared__ int   red[256];
    __shared__ int   sh_sel[2];
    __shared__ float fred[8];

    int tid = threadIdx.x, lane = tid & 31, wid = tid >> 5;

    float r[8]; unsigned u[8];
    {
        float4 v0 = *(const float4*)&row[tid * 8];
        float4 v1 = *(const float4*)&row[tid * 8 + 4];
        r[0] = v0.x; r[1] = v0.y; r[2] = v0.z; r[3] = v0.w;
        r[4] = v1.x; r[5] = v1.y; r[6] = v1.z; r[7] = v1.w;
    }
#pragma unroll
    for (int e = 0; e < 8; e++) u[e] = __float_as_uint(fabsf(r[e]));

    unsigned prefix = 0;
    int kneed = KK;
#pragma unroll
    for (int byte = 3; byte >= 0; --byte) {
        for (int b = lane; b < 256; b += 32) hist[wid][b] = 0;
        __syncthreads();
        unsigned pm = (byte == 3) ? 0u : (0xFFFFFFFFu << (8 * (byte + 1)));
#pragma unroll
        for (int e = 0; e < 8; e++)
            if ((u[e] & pm) == prefix)
                atomicAdd(&hist[wid][(u[e] >> (8 * byte)) & 255], 1);
        __syncthreads();
        int cnt = 0;
#pragma unroll
        for (int w = 0; w < 8; w++) cnt += hist[w][tid];
        red[tid] = cnt;
        __syncthreads();
        if (wid == 0) {
            int v[8], cum[8], s = 0;
#pragma unroll
            for (int e = 0; e < 8; e++) {
                v[e] = red[255 - (lane * 8 + e)];
                s += v[e];
                cum[e] = s;
            }
            int incl = s;
#pragma unroll
            for (int off = 1; off < 32; off <<= 1) {
                int t2 = __shfl_up_sync(FULLM, incl, off);
                if (lane >= off) incl += t2;
            }
            int excl = incl - s;
            bool has = (excl + cum[7]) >= kneed && excl < kneed;
            unsigned bal = __ballot_sync(FULLM, has);
            int fl = __ffs(bal) - 1;
            if (lane == fl) {
                int e = 0;
                while (excl + cum[e] < kneed) e++;
                sh_sel[0] = 255 - (lane * 8 + e);
                sh_sel[1] = kneed - (excl + cum[e] - v[e]);
            }
        }
        __syncthreads();
        prefix |= ((unsigned)sh_sel[0]) << (8 * byte);
        kneed = sh_sel[1];
        __syncthreads();
    }
    unsigned T = prefix;

    int jmax = i + WINDOW;
    float m = -INFINITY;
    float sv[8];
#pragma unroll
    for (int e = 0; e < 8; e++) {
        int j = tid * 8 + e;
        bool keep = (j <= jmax) && (u[e] >= T);
        sv[e] = keep ? r[e] : -INFINITY;
        m = fmaxf(m, sv[e]);
    }
#pragma unroll
    for (int off = 16; off; off >>= 1)
        m = fmaxf(m, __shfl_xor_sync(FULLM, m, off));
    if (lane == 0) fred[wid] = m;
    __syncthreads();
    float mm = -INFINITY;
#pragma unroll
    for (int w = 0; w < 8; w++) mm = fmaxf(mm, fred[w]);
    __syncthreads();

    float z = 0.f;
    float ex[8];
#pragma unroll
    for (int e = 0; e < 8; e++) {
        ex[e] = (sv[e] == -INFINITY) ? 0.f : __expf(sv[e] - mm);
        z += ex[e];
    }
#pragma unroll
    for (int off = 16; off; off >>= 1)
        z += __shfl_xor_sync(FULLM, z, off);
    if (lane == 0) fred[wid] = z;
    __syncthreads();
    float zz = 0.f;
#pragma unroll
    for (int w = 0; w < 8; w++) zz += fred[w];
    float inv = (zz > 0.f) ? 1.f / zz : 0.f;

    // PV (BM=64, band=192) only reads j < (i&~63)+192; rest stays unread.
    int limit = (i & ~63) + 192;
    if (tid * 8 < limit) {
        float4 o0 = make_float4(ex[0] * inv, ex[1] * inv, ex[2] * inv, ex[3] * inv);
        float4 o1 = make_float4(ex[4] * inv, ex[5] * inv, ex[6] * inv, ex[7] * inv);
        *(float4*)&row[tid * 8]     = o0;
        *(float4*)&row[tid * 8 + 4] = o1;
    }
}

// ---------------------------------------------------------------------------
// Launch
// ---------------------------------------------------------------------------
extern "C" void kernel_launch(void* const* d_in, const int* in_sizes, int n_in,
                              void* d_out, int out_size)
{
    const float* x      = (const float*)d_in[0];
    const float* Amat   = (const float*)d_in[1];
    const float* Bm     = (const float*)d_in[2];
    const float* Cm     = (const float*)d_in[3];
    const float* log_dt = (const float*)d_in[4];
    const float* Wg = (const float*)d_in[5];  const float* bg = (const float*)d_in[6];
    const float* Wq = (const float*)d_in[7];  const float* bq = (const float*)d_in[8];
    const float* Wk = (const float*)d_in[9];  const float* bk = (const float*)d_in[10];
    const float* Wv = (const float*)d_in[11]; const float* bv = (const float*)d_in[12];
    const float* Wd = (const float*)d_in[13]; const float* bd = (const float*)d_in[14];
    float* out = (float*)d_out;

    float *gate, *H, *Q, *K, *V, *ctx, *scores;
    cudaGetSymbolAddress((void**)&gate,   g_gate);
    cudaGetSymbolAddress((void**)&H,      g_H);
    cudaGetSymbolAddress((void**)&Q,      g_Q);
    cudaGetSymbolAddress((void**)&K,      g_K);
    cudaGetSymbolAddress((void**)&V,      g_V);
    cudaGetSymbolAddress((void**)&ctx,    g_ctx);
    cudaGetSymbolAddress((void**)&scores, g_scores);

    cudaFuncSetAttribute(gemm_tc128<1>, cudaFuncAttributeMaxDynamicSharedMemorySize, SM128);
    cudaFuncSetAttribute(gemm_tc128<2>, cudaFuncAttributeMaxDynamicSharedMemorySize, SM128);

    dim3 blk(256);

    // 1) gate = sigmoid(X Wg^T + bg)
    {
        dim3 grid(D_DIM / 64, S_LEN / 128, 1);
        gemm_tc128<2><<<grid, blk, SM128>>>(x, Wg, Wg, Wg, bg, bg, bg,
            gate, gate, gate, D_DIM, D_DIM, D_DIM, D_DIM, D_DIM / 64);
    }
    // 2) SSM scan -> H = x + y
    ssm_kernel<<<D_DIM / 8, 128>>>(x, gate, Amat, Bm, Cm, log_dt, H);

    // 3) Fused Q,K,V projections
    {
        dim3 grid(3 * D_DIM / 64, S_LEN / 128, 1);
        gemm_tc128<1><<<grid, blk, SM128>>>(H, Wq, Wk, Wv, bq, bk, bv,
            Q, K, V, D_DIM, D_DIM, D_DIM, D_DIM, D_DIM / 64);
    }
    // 4) scores[h] = Q_h K_h^T / 8
    {
        dim3 grid(S_LEN / 64, S_LEN / 64, N_HEADS);
        gemm_tc<true, 0, 1><<<grid, blk>>>(Q, K, scores,
            DH, D_DIM, D_DIM, S_LEN,
            DH, DH, (long)S_LEN * S_LEN, 0.125f, 0);
    }
    // 5) per-row top-k select + masks + softmax (in place, banded writes)
    {
        dim3 grid(S_LEN, N_HEADS);
        mask_softmax_kernel<<<grid, blk>>>(scores);
    }
    // 6) ctx[h] = P_h V_h   (banded, split-K=2, atomic adds)
    {
        cudaMemsetAsync(ctx, 0, (size_t)S_LEN * D_DIM * sizeof(float));
        dim3 grid(DH / 64, S_LEN / 64, N_HEADS * 2);
        gemm_tc<false, 3, 2><<<grid, blk>>>(scores, V, ctx,
            S_LEN, S_LEN, D_DIM, D_DIM,
            (long)S_LEN * S_LEN, DH, DH, 1.f, 64 + WINDOW);
    }
    // 7) out = ctx Wd^T + bd
    {
        dim3 grid(D_DIM / 64, S_LEN / 128, 1);
        gemm_tc128<1><<<grid, blk, SM128>>>(ctx, Wd, Wd, Wd, bd, bd, bd,
            out, out, out, D_DIM, D_DIM, D_DIM, D_DIM, D_DIM / 64);
    }
}

// round 16
// speedup vs baseline: 1.2635x; 1.0130x over previous
#include <cuda_runtime.h>
#include <cuda_bf16.h>
#include <math.h>
#include <stdint.h>

// Problem constants
#define S_LEN 2048
#define D_DIM 768
#define N_STATE 16
#define N_HEADS 12
#define DH 64
#define WINDOW 128
#define KK 1843            // int((1-0.1)*2048)
#define SPIKE 0.1f
#define FULLM 0xffffffffu

// ---------------------------------------------------------------------------
// Scratch (device globals; no dynamic allocation allowed)
// ---------------------------------------------------------------------------
__device__ float g_gate[S_LEN * D_DIM];
__device__ float g_H[S_LEN * D_DIM];
__device__ float g_Q[S_LEN * D_DIM];
__device__ float g_K[S_LEN * D_DIM];
__device__ float g_V[S_LEN * D_DIM];
__device__ float g_ctx[S_LEN * D_DIM];
__device__ float g_scores[(size_t)N_HEADS * S_LEN * S_LEN];   // 192 MB

// ---------------------------------------------------------------------------
// Split-TF32 helpers (3-MMA emulation of fp32 GEMM on tensor cores)
// ---------------------------------------------------------------------------
__device__ __forceinline__ void split_tf32(float a, uint32_t& hi, uint32_t& lo) {
    asm("cvt.rna.tf32.f32 %0, %1;" : "=r"(hi) : "f"(a));
    float r = a - __uint_as_float(hi);
    asm("cvt.rna.tf32.f32 %0, %1;" : "=r"(lo) : "f"(r));
}

__device__ __forceinline__ void mma8(float c[4], const uint32_t a[4], const uint32_t b[2]) {
    asm("mma.sync.aligned.m16n8k8.row.col.f32.tf32.tf32.f32 "
        "{%0,%1,%2,%3},{%4,%5,%6,%7},{%8,%9},{%0,%1,%2,%3};"
        : "+f"(c[0]), "+f"(c[1]), "+f"(c[2]), "+f"(c[3])
        : "r"(a[0]), "r"(a[1]), "r"(a[2]), "r"(a[3]), "r"(b[0]), "r"(b[1]));
}

#define CPA16(dst, src) asm volatile("cp.async.ca.shared.global [%0], [%1], 16;" :: "r"(dst), "l"(src))
#define CPCOMMIT()      asm volatile("cp.async.commit_group;" ::: "memory")
#define CPWAIT1()       asm volatile("cp.async.wait_group 1;" ::: "memory")
#define CPWAIT0()       asm volatile("cp.async.wait_group 0;" ::: "memory")

// ---------------------------------------------------------------------------
// BM=64 GEMM (split tf32, 3-MMA). Used for PV (!BT, banded, split-K).
// ---------------------------------------------------------------------------
template<bool BT, int EPI, int SPLITK>
__global__ __launch_bounds__(256)
void gemm_tc(const float* __restrict__ A, const float* __restrict__ B,
             float* __restrict__ C,
             int K, int lda, int ldb, int ldc,
             long Astride, long Bstride, long Cstride,
             float alpha, int band)
{
    const int BK = 32;
    __shared__ float As[2][64 * 36];
    __shared__ float Bs[2][64 * 36];

    int bz   = blockIdx.z / SPLITK;
    int part = blockIdx.z % SPLITK;
    A += (long)bz * Astride;
    B += (long)bz * Bstride;
    C += (long)bz * Cstride;

    int tid  = threadIdx.x;
    int lane = tid & 31;
    int wid  = tid >> 5;
    int wm   = wid >> 2;
    int wn   = wid & 3;
    int g    = lane >> 2;
    int tg   = lane & 3;

    int row0 = blockIdx.y * 64;
    int col0 = blockIdx.x * 64;

    unsigned asb = (unsigned)__cvta_generic_to_shared(&As[0][0]);
    unsigned bsb = (unsigned)__cvta_generic_to_shared(&Bs[0][0]);

    float c[2][2][4];
#pragma unroll
    for (int mi = 0; mi < 2; mi++)
#pragma unroll
        for (int ni = 0; ni < 2; ni++)
#pragma unroll
            for (int r = 0; r < 4; r++) c[mi][ni][r] = 0.f;

    int Keff  = band > 0 ? min(K, row0 + band) : K;
    int tiles = Keff / BK;
    int tA = (tiles * part) / SPLITK;
    int tB = (tiles * (part + 1)) / SPLITK;
    int T  = tB - tA;

    auto load_tile = [&](int tk, int st) {
        int k0 = tk * BK;
        unsigned ad = asb + st * (64 * 36 * 4);
        unsigned bd = bsb + st * (64 * 36 * 4);
#pragma unroll
        for (int i = 0; i < 2; i++) {
            int idx = tid + i * 256;
            int m = idx >> 3, kc = (idx & 7) << 2;
            CPA16(ad + (m * 36 + kc) * 4, &A[(long)(row0 + m) * lda + k0 + kc]);
        }
        if (BT) {
#pragma unroll
            for (int i = 0; i < 2; i++) {
                int idx = tid + i * 256;
                int n = idx >> 3, kc = (idx & 7) << 2;
                CPA16(bd + (n * 36 + kc) * 4, &B[(long)(col0 + n) * ldb + k0 + kc]);
            }
        } else {
#pragma unroll
            for (int i = 0; i < 2; i++) {
                int idx = tid + i * 256;
                int kk = idx >> 4, nc = (idx & 15) << 2;
                CPA16(bd + (kk * 72 + nc) * 4, &B[(long)(k0 + kk) * ldb + col0 + nc]);
            }
        }
        CPCOMMIT();
    };

    if (T > 0) load_tile(tA, 0);

    for (int t = 0; t < T; t++) {
        if (t + 1 < T) { load_tile(tA + t + 1, (t + 1) & 1); CPWAIT1(); }
        else           { CPWAIT0(); }
        __syncthreads();

        const float* as = As[t & 1];
        const float* bs = Bs[t & 1];
#pragma unroll
        for (int ks = 0; ks < BK; ks += 8) {
            uint32_t ah[2][4], al[2][4];
#pragma unroll
            for (int mi = 0; mi < 2; mi++) {
                int mb = wm * 32 + mi * 16;
                split_tf32(as[(mb + g)     * 36 + ks + tg],     ah[mi][0], al[mi][0]);
                split_tf32(as[(mb + g + 8) * 36 + ks + tg],     ah[mi][1], al[mi][1]);
                split_tf32(as[(mb + g)     * 36 + ks + tg + 4], ah[mi][2], al[mi][2]);
                split_tf32(as[(mb + g + 8) * 36 + ks + tg + 4], ah[mi][3], al[mi][3]);
            }
            uint32_t bh[2][2], bl[2][2];
#pragma unroll
            for (int ni = 0; ni < 2; ni++) {
                int nb = wn * 16 + ni * 8 + g;
                float f0 = BT ? bs[nb * 36 + ks + tg]     : bs[(ks + tg)     * 72 + nb];
                float f1 = BT ? bs[nb * 36 + ks + tg + 4] : bs[(ks + tg + 4) * 72 + nb];
                split_tf32(f0, bh[ni][0], bl[ni][0]);
                split_tf32(f1, bh[ni][1], bl[ni][1]);
            }
#pragma unroll
            for (int mi = 0; mi < 2; mi++)
#pragma unroll
                for (int ni = 0; ni < 2; ni++) {
                    mma8(c[mi][ni], ah[mi], bh[ni]);
                    mma8(c[mi][ni], ah[mi], bl[ni]);
                    mma8(c[mi][ni], al[mi], bh[ni]);
                }
        }
        __syncthreads();
    }

#pragma unroll
    for (int mi = 0; mi < 2; mi++) {
#pragma unroll
        for (int ni = 0; ni < 2; ni++) {
            int row = row0 + wm * 32 + mi * 16 + g;
            int col = col0 + wn * 16 + ni * 8 + 2 * tg;
            float v0 = c[mi][ni][0] * alpha;
            float v1 = c[mi][ni][1] * alpha;
            float v2 = c[mi][ni][2] * alpha;
            float v3 = c[mi][ni][3] * alpha;
            if (EPI == 3) {
                atomicAdd(&C[(long)row * ldc + col],           v0);
                atomicAdd(&C[(long)row * ldc + col + 1],       v1);
                atomicAdd(&C[(long)(row + 8) * ldc + col],     v2);
                atomicAdd(&C[(long)(row + 8) * ldc + col + 1], v3);
            } else {
                *(float2*)&C[(long)row * ldc + col]       = make_float2(v0, v1);
                *(float2*)&C[(long)(row + 8) * ldc + col] = make_float2(v2, v3);
            }
        }
    }
}

// ---------------------------------------------------------------------------
// BM=128 x BN=64 GEMM (split tf32, 3-MMA), BT only:
//   C[m,n] = alpha * sum_k A[m,k]*B[n,k] (+bias) (+sigmoid)
// 2-stage cp.async, dynamic smem (55.3 KB). 8 warps 4m x 2n, 32x32/warp.
// B/bias/C selected by blockIdx.x / nper (fused QKV). Per-z batch strides.
// ---------------------------------------------------------------------------
#define SM128 (2 * (128 * 36 + 64 * 36) * 4)

template<int EPI>
__global__ __launch_bounds__(256)
void gemm_tc128(const float* __restrict__ A,
                const float* __restrict__ B0, const float* __restrict__ B1,
                const float* __restrict__ B2,
                const float* __restrict__ bi0, const float* __restrict__ bi1,
                const float* __restrict__ bi2,
                float* __restrict__ C0, float* __restrict__ C1, float* __restrict__ C2,
                int K, int lda, int ldb, int ldc, int nper,
                long Astride, long Bstride, long Cstride, float alpha)
{
    extern __shared__ float sm[];
    float* As = sm;                    // 2 stages x 128*36
    float* Bs = sm + 2 * 128 * 36;     // 2 stages x 64*36

    int sel = blockIdx.x / nper;
    int xb  = blockIdx.x % nper;
    const float* B    = (sel == 0) ? B0  : (sel == 1) ? B1  : B2;
    const float* bias = (sel == 0) ? bi0 : (sel == 1) ? bi1 : bi2;
    float*       C    = (sel == 0) ? C0  : (sel == 1) ? C1  : C2;

    A += (long)blockIdx.z * Astride;
    B += (long)blockIdx.z * Bstride;
    C += (long)blockIdx.z * Cstride;

    const int BK = 32;
    int tid  = threadIdx.x;
    int lane = tid & 31;
    int wid  = tid >> 5;
    int wm   = wid >> 1;              // 0..3
    int wn   = wid & 1;               // 0..1
    int g    = lane >> 2;
    int tg   = lane & 3;

    int row0 = blockIdx.y * 128;
    int col0 = xb * 64;

    unsigned asb = (unsigned)__cvta_generic_to_shared(As);
    unsigned bsb = (unsigned)__cvta_generic_to_shared(Bs);

    float c[2][4][4];
#pragma unroll
    for (int mi = 0; mi < 2; mi++)
#pragma unroll
        for (int ni = 0; ni < 4; ni++)
#pragma unroll
            for (int r = 0; r < 4; r++) c[mi][ni][r] = 0.f;

    int T = K / BK;

    auto load_tile = [&](int tk, int st) {
        int k0 = tk * BK;
        unsigned ad = asb + st * (128 * 36 * 4);
        unsigned bd = bsb + st * (64 * 36 * 4);
#pragma unroll
        for (int i = 0; i < 4; i++) {
            int idx = tid + i * 256;           // 1024 float4
            int m = idx >> 3, kc = (idx & 7) << 2;
            CPA16(ad + (m * 36 + kc) * 4, &A[(long)(row0 + m) * lda + k0 + kc]);
        }
#pragma unroll
        for (int i = 0; i < 2; i++) {
            int idx = tid + i * 256;           // 512 float4
            int n = idx >> 3, kc = (idx & 7) << 2;
            CPA16(bd + (n * 36 + kc) * 4, &B[(long)(col0 + n) * ldb + k0 + kc]);
        }
        CPCOMMIT();
    };

    load_tile(0, 0);

    for (int t = 0; t < T; t++) {
        if (t + 1 < T) { load_tile(t + 1, (t + 1) & 1); CPWAIT1(); }
        else           { CPWAIT0(); }
        __syncthreads();

        const float* as = As + (t & 1) * 128 * 36;
        const float* bs = Bs + (t & 1) * 64 * 36;
#pragma unroll
        for (int ks = 0; ks < BK; ks += 8) {
            uint32_t ah[2][4], al[2][4];
#pragma unroll
            for (int mi = 0; mi < 2; mi++) {
                int mb = wm * 32 + mi * 16;
                split_tf32(as[(mb + g)     * 36 + ks + tg],     ah[mi][0], al[mi][0]);
                split_tf32(as[(mb + g + 8) * 36 + ks + tg],     ah[mi][1], al[mi][1]);
                split_tf32(as[(mb + g)     * 36 + ks + tg + 4], ah[mi][2], al[mi][2]);
                split_tf32(as[(mb + g + 8) * 36 + ks + tg + 4], ah[mi][3], al[mi][3]);
            }
            uint32_t bh[4][2], bl[4][2];
#pragma unroll
            for (int ni = 0; ni < 4; ni++) {
                int nb = wn * 32 + ni * 8 + g;
                split_tf32(bs[nb * 36 + ks + tg],     bh[ni][0], bl[ni][0]);
                split_tf32(bs[nb * 36 + ks + tg + 4], bh[ni][1], bl[ni][1]);
            }
#pragma unroll
            for (int mi = 0; mi < 2; mi++)
#pragma unroll
                for (int ni = 0; ni < 4; ni++) {
                    mma8(c[mi][ni], ah[mi], bh[ni]);
                    mma8(c[mi][ni], ah[mi], bl[ni]);
                    mma8(c[mi][ni], al[mi], bh[ni]);
                }
        }
        __syncthreads();
    }

#pragma unroll
    for (int mi = 0; mi < 2; mi++) {
#pragma unroll
        for (int ni = 0; ni < 4; ni++) {
            int row = row0 + wm * 32 + mi * 16 + g;
            int col = col0 + wn * 32 + ni * 8 + 2 * tg;
            float v0 = c[mi][ni][0] * alpha;
            float v1 = c[mi][ni][1] * alpha;
            float v2 = c[mi][ni][2] * alpha;
            float v3 = c[mi][ni][3] * alpha;
            if (EPI >= 1) {
                float b0 = bias[col], b1 = bias[col + 1];
                v0 += b0; v1 += b1; v2 += b0; v3 += b1;
            }
            if (EPI == 2) {
                v0 = 1.f / (1.f + expf(-v0));
                v1 = 1.f / (1.f + expf(-v1));
                v2 = 1.f / (1.f + expf(-v2));
                v3 = 1.f / (1.f + expf(-v3));
            }
            *(float2*)&C[(long)row * ldc + col]       = make_float2(v0, v1);
            *(float2*)&C[(long)(row + 8) * ldc + col] = make_float2(v2, v3);
        }
    }
}

// ---------------------------------------------------------------------------
// SSM sequential scan. 16 lanes per channel (lane = state index n).
// ---------------------------------------------------------------------------
__global__ __launch_bounds__(128)
void ssm_kernel(const float* __restrict__ x, const float* __restrict__ gate,
                const float* __restrict__ Amat, const float* __restrict__ Bm,
                const float* __restrict__ Cm, const float* __restrict__ log_dt,
                float* __restrict__ Hout)
{
    int lane = threadIdx.x & 15;
    int d = blockIdx.x * (blockDim.x >> 4) + (threadIdx.x >> 4);
    if (d >= D_DIM) return;

    float Arow[N_STATE];
#pragma unroll
    for (int m = 0; m < N_STATE; m++) Arow[m] = Amat[lane * N_STATE + m];
    float Bn  = Bm[lane * D_DIM + d];
    float Cn  = Cm[d * N_STATE + lane];
    float dtd = fminf(fmaxf(expf(log_dt[d]), 1e-3f), 1e-1f);

    float h  = 0.f;
    float xv = __ldg(&x[d]);
    float gv = __ldg(&gate[d]);

    for (int t = 0; t < S_LEN; t++) {
        float xn = 0.f, gn = 0.f;
        if (t + 1 < S_LEN) {
            xn = __ldg(&x[(t + 1) * D_DIM + d]);
            gn = __ldg(&gate[(t + 1) * D_DIM + d]);
        }
        float p0 = 0.f, p1 = 0.f, p2 = 0.f, p3 = 0.f;
#pragma unroll
        for (int m = 0; m < 4; m++) {
            p0 = fmaf(Arow[m],      __shfl_sync(FULLM, h, m,      16), p0);
            p1 = fmaf(Arow[m + 4],  __shfl_sync(FULLM, h, m + 4,  16), p1);
            p2 = fmaf(Arow[m + 8],  __shfl_sync(FULLM, h, m + 8,  16), p2);
            p3 = fmaf(Arow[m + 12], __shfl_sync(FULLM, h, m + 12, 16), p3);
        }
        float acc = (p0 + p1) + (p2 + p3);
        float sc  = (acc + xv * Bn) * dtd;
        float gm  = (fabsf(sc) > SPIKE) ? gv : 0.f;
        h = fmaf(sc, gm, h);

        float pr = h * Cn;
#pragma unroll
        for (int off = 8; off; off >>= 1)
            pr += __shfl_xor_sync(FULLM, pr, off, 16);
        if (lane == 0) Hout[t * D_DIM + d] = xv + pr;

        xv = xn; gv = gn;
    }
}

// ---------------------------------------------------------------------------
// Per-row: radix-select kk-th largest |score|, local+sparse mask, softmax.
// Row in registers; per-warp histograms; warp-0 shuffle suffix-scan.
// Writes only the banded region read by PV (j < (i&~63)+192).
// ---------------------------------------------------------------------------
__global__ __launch_bounds__(256)
void mask_softmax_kernel(float* __restrict__ scores)
{
    int i  = blockIdx.x;
    int hd = blockIdx.y;
    float* row = scores + ((size_t)hd * S_LEN + i) * S_LEN;

    __shared__ int   hist[8][256];
    __shared__ int   red[256];
    __shared__ int   sh_sel[2];
    __shared__ float fred[8];

    int tid = threadIdx.x, lane = tid & 31, wid = tid >> 5;

    float r[8]; unsigned u[8];
    {
        float4 v0 = *(const float4*)&row[tid * 8];
        float4 v1 = *(const float4*)&row[tid * 8 + 4];
        r[0] = v0.x; r[1] = v0.y; r[2] = v0.z; r[3] = v0.w;
        r[4] = v1.x; r[5] = v1.y; r[6] = v1.z; r[7] = v1.w;
    }
#pragma unroll
    for (int e = 0; e < 8; e++) u[e] = __float_as_uint(fabsf(r[e]));

    unsigned prefix = 0;
    int kneed = KK;
#pragma unroll
    for (int byte = 3; byte >= 0; --byte) {
        for (int b = lane; b < 256; b += 32) hist[wid][b] = 0;
        __syncthreads();
        unsigned pm = (byte == 3) ? 0u : (0xFFFFFFFFu << (8 * (byte + 1)));
#pragma unroll
        for (int e = 0; e < 8; e++)
            if ((u[e] & pm) == prefix)
                atomicAdd(&hist[wid][(u[e] >> (8 * byte)) & 255], 1);
        __syncthreads();
        int cnt = 0;
#pragma unroll
        for (int w = 0; w < 8; w++) cnt += hist[w][tid];
        red[tid] = cnt;
        __syncthreads();
        if (wid == 0) {
            int v[8], cum[8], s = 0;
#pragma unroll
            for (int e = 0; e < 8; e++) {
                v[e] = red[255 - (lane * 8 + e)];
                s += v[e];
                cum[e] = s;
            }
            int incl = s;
#pragma unroll
            for (int off = 1; off < 32; off <<= 1) {
                int t2 = __shfl_up_sync(FULLM, incl, off);
                if (lane >= off) incl += t2;
            }
            int excl = incl - s;
            bool has = (excl + cum[7]) >= kneed && excl < kneed;
            unsigned bal = __ballot_sync(FULLM, has);
            int fl = __ffs(bal) - 1;
            if (lane == fl) {
                int e = 0;
                while (excl + cum[e] < kneed) e++;
                sh_sel[0] = 255 - (lane * 8 + e);
                sh_sel[1] = kneed - (excl + cum[e] - v[e]);
            }
        }
        __syncthreads();
        prefix |= ((unsigned)sh_sel[0]) << (8 * byte);
        kneed = sh_sel[1];
        __syncthreads();
    }
    unsigned T = prefix;

    int jmax = i + WINDOW;
    float m = -INFINITY;
    float sv[8];
#pragma unroll
    for (int e = 0; e < 8; e++) {
        int j = tid * 8 + e;
        bool keep = (j <= jmax) && (u[e] >= T);
        sv[e] = keep ? r[e] : -INFINITY;
        m = fmaxf(m, sv[e]);
    }
#pragma unroll
    for (int off = 16; off; off >>= 1)
        m = fmaxf(m, __shfl_xor_sync(FULLM, m, off));
    if (lane == 0) fred[wid] = m;
    __syncthreads();
    float mm = -INFINITY;
#pragma unroll
    for (int w = 0; w < 8; w++) mm = fmaxf(mm, fred[w]);
    __syncthreads();

    float z = 0.f;
    float ex[8];
#pragma unroll
    for (int e = 0; e < 8; e++) {
        ex[e] = (sv[e] == -INFINITY) ? 0.f : __expf(sv[e] - mm);
        z += ex[e];
    }
#pragma unroll
    for (int off = 16; off; off >>= 1)
        z += __shfl_xor_sync(FULLM, z, off);
    if (lane == 0) fred[wid] = z;
    __syncthreads();
    float zz = 0.f;
#pragma unroll
    for (int w = 0; w < 8; w++) zz += fred[w];
    float inv = (zz > 0.f) ? 1.f / zz : 0.f;

    // PV (BM=64, band=192) only reads j < (i&~63)+192; rest stays unread.
    int limit = (i & ~63) + 192;
    if (tid * 8 < limit) {
        float4 o0 = make_float4(ex[0] * inv, ex[1] * inv, ex[2] * inv, ex[3] * inv);
        float4 o1 = make_float4(ex[4] * inv, ex[5] * inv, ex[6] * inv, ex[7] * inv);
        *(float4*)&row[tid * 8]     = o0;
        *(float4*)&row[tid * 8 + 4] = o1;
    }
}

// ---------------------------------------------------------------------------
// Launch
// ---------------------------------------------------------------------------
extern "C" void kernel_launch(void* const* d_in, const int* in_sizes, int n_in,
                              void* d_out, int out_size)
{
    const float* x      = (const float*)d_in[0];
    const float* Amat   = (const float*)d_in[1];
    const float* Bm     = (const float*)d_in[2];
    const float* Cm     = (const float*)d_in[3];
    const float* log_dt = (const float*)d_in[4];
    const float* Wg = (const float*)d_in[5];  const float* bg = (const float*)d_in[6];
    const float* Wq = (const float*)d_in[7];  const float* bq = (const float*)d_in[8];
    const float* Wk = (const float*)d_in[9];  const float* bk = (const float*)d_in[10];
    const float* Wv = (const float*)d_in[11]; const float* bv = (const float*)d_in[12];
    const float* Wd = (const float*)d_in[13]; const float* bd = (const float*)d_in[14];
    float* out = (float*)d_out;

    float *gate, *H, *Q, *K, *V, *ctx, *scores;
    cudaGetSymbolAddress((void**)&gate,   g_gate);
    cudaGetSymbolAddress((void**)&H,      g_H);
    cudaGetSymbolAddress((void**)&Q,      g_Q);
    cudaGetSymbolAddress((void**)&K,      g_K);
    cudaGetSymbolAddress((void**)&V,      g_V);
    cudaGetSymbolAddress((void**)&ctx,    g_ctx);
    cudaGetSymbolAddress((void**)&scores, g_scores);

    cudaFuncSetAttribute(gemm_tc128<0>, cudaFuncAttributeMaxDynamicSharedMemorySize, SM128);
    cudaFuncSetAttribute(gemm_tc128<1>, cudaFuncAttributeMaxDynamicSharedMemorySize, SM128);
    cudaFuncSetAttribute(gemm_tc128<2>, cudaFuncAttributeMaxDynamicSharedMemorySize, SM128);

    dim3 blk(256);

    // 1) gate = sigmoid(X Wg^T + bg)
    {
        dim3 grid(D_DIM / 64, S_LEN / 128, 1);
        gemm_tc128<2><<<grid, blk, SM128>>>(x, Wg, Wg, Wg, bg, bg, bg,
            gate, gate, gate, D_DIM, D_DIM, D_DIM, D_DIM, D_DIM / 64,
            0, 0, 0, 1.f);
    }
    // 2) SSM scan -> H = x + y
    ssm_kernel<<<D_DIM / 8, 128>>>(x, gate, Amat, Bm, Cm, log_dt, H);

    // 3) Fused Q,K,V projections
    {
        dim3 grid(3 * D_DIM / 64, S_LEN / 128, 1);
        gemm_tc128<1><<<grid, blk, SM128>>>(H, Wq, Wk, Wv, bq, bk, bv,
            Q, K, V, D_DIM, D_DIM, D_DIM, D_DIM, D_DIM / 64,
            0, 0, 0, 1.f);
    }
    // 4) scores[h] = Q_h K_h^T / 8   (BM=128: 2.0 ALU/MMA vs 3.0 at BM=64)
    {
        dim3 grid(S_LEN / 64, S_LEN / 128, N_HEADS);
        gemm_tc128<0><<<grid, blk, SM128>>>(Q, K, K, K,
            nullptr, nullptr, nullptr, scores, scores, scores,
            DH, D_DIM, D_DIM, S_LEN, S_LEN / 64,
            DH, DH, (long)S_LEN * S_LEN, 0.125f);
    }
    // 5) per-row top-k select + masks + softmax (in place, banded writes)
    {
        dim3 grid(S_LEN, N_HEADS);
        mask_softmax_kernel<<<grid, blk>>>(scores);
    }
    // 6) ctx[h] = P_h V_h   (banded, split-K=2, atomic adds)
    {
        cudaMemsetAsync(ctx, 0, (size_t)S_LEN * D_DIM * sizeof(float));
        dim3 grid(DH / 64, S_LEN / 64, N_HEADS * 2);
        gemm_tc<false, 3, 2><<<grid, blk>>>(scores, V, ctx,
            S_LEN, S_LEN, D_DIM, D_DIM,
            (long)S_LEN * S_LEN, DH, DH, 1.f, 64 + WINDOW);
    }
    // 7) out = ctx Wd^T + bd
    {
        dim3 grid(D_DIM / 64, S_LEN / 128, 1);
        gemm_tc128<1><<<grid, blk, SM128>>>(ctx, Wd, Wd, Wd, bd, bd, bd,
            out, out, out, D_DIM, D_DIM, D_DIM, D_DIM, D_DIM / 64,
            0, 0, 0, 1.f);
    }
}

// round 17
// speedup vs baseline: 1.2903x; 1.0212x over previous
#include <cuda_runtime.h>
#include <cuda_bf16.h>
#include <math.h>
#include <stdint.h>

// Problem constants
#define S_LEN 2048
#define D_DIM 768
#define N_STATE 16
#define N_HEADS 12
#define DH 64
#define WINDOW 128
#define KK 1843            // int((1-0.1)*2048)
#define SPIKE 0.1f
#define FULLM 0xffffffffu

// ---------------------------------------------------------------------------
// Scratch (device globals; no dynamic allocation allowed)
// ---------------------------------------------------------------------------
__device__ float g_gate[S_LEN * D_DIM];
__device__ float g_H[S_LEN * D_DIM];
__device__ float g_Q[S_LEN * D_DIM];
__device__ float g_K[S_LEN * D_DIM];
__device__ float g_V[S_LEN * D_DIM];
__device__ float g_ctx[S_LEN * D_DIM];
__device__ float g_scores[(size_t)N_HEADS * S_LEN * S_LEN];   // 192 MB

// ---------------------------------------------------------------------------
// Split-TF32 helpers (3-MMA emulation of fp32 GEMM on tensor cores)
// ---------------------------------------------------------------------------
__device__ __forceinline__ void split_tf32(float a, uint32_t& hi, uint32_t& lo) {
    asm("cvt.rna.tf32.f32 %0, %1;" : "=r"(hi) : "f"(a));
    float r = a - __uint_as_float(hi);
    asm("cvt.rna.tf32.f32 %0, %1;" : "=r"(lo) : "f"(r));
}

__device__ __forceinline__ void mma8(float c[4], const uint32_t a[4], const uint32_t b[2]) {
    asm("mma.sync.aligned.m16n8k8.row.col.f32.tf32.tf32.f32 "
        "{%0,%1,%2,%3},{%4,%5,%6,%7},{%8,%9},{%0,%1,%2,%3};"
        : "+f"(c[0]), "+f"(c[1]), "+f"(c[2]), "+f"(c[3])
        : "r"(a[0]), "r"(a[1]), "r"(a[2]), "r"(a[3]), "r"(b[0]), "r"(b[1]));
}

#define CPA16(dst, src) asm volatile("cp.async.ca.shared.global [%0], [%1], 16;" :: "r"(dst), "l"(src))
#define CPCOMMIT()      asm volatile("cp.async.commit_group;" ::: "memory")
#define CPWAIT1()       asm volatile("cp.async.wait_group 1;" ::: "memory")
#define CPWAIT0()       asm volatile("cp.async.wait_group 0;" ::: "memory")

// ---------------------------------------------------------------------------
// BM=64 GEMM (split tf32, 3-MMA). Used for PV (!BT, banded, split-K).
// ---------------------------------------------------------------------------
template<bool BT, int EPI, int SPLITK>
__global__ __launch_bounds__(256)
void gemm_tc(const float* __restrict__ A, const float* __restrict__ B,
             float* __restrict__ C,
             int K, int lda, int ldb, int ldc,
             long Astride, long Bstride, long Cstride,
             float alpha, int band)
{
    const int BK = 32;
    __shared__ float As[2][64 * 36];
    __shared__ float Bs[2][64 * 36];

    int bz   = blockIdx.z / SPLITK;
    int part = blockIdx.z % SPLITK;
    A += (long)bz * Astride;
    B += (long)bz * Bstride;
    C += (long)bz * Cstride;

    int tid  = threadIdx.x;
    int lane = tid & 31;
    int wid  = tid >> 5;
    int wm   = wid >> 2;
    int wn   = wid & 3;
    int g    = lane >> 2;
    int tg   = lane & 3;

    int row0 = blockIdx.y * 64;
    int col0 = blockIdx.x * 64;

    unsigned asb = (unsigned)__cvta_generic_to_shared(&As[0][0]);
    unsigned bsb = (unsigned)__cvta_generic_to_shared(&Bs[0][0]);

    float c[2][2][4];
#pragma unroll
    for (int mi = 0; mi < 2; mi++)
#pragma unroll
        for (int ni = 0; ni < 2; ni++)
#pragma unroll
            for (int r = 0; r < 4; r++) c[mi][ni][r] = 0.f;

    int Keff  = band > 0 ? min(K, row0 + band) : K;
    int tiles = Keff / BK;
    int tA = (tiles * part) / SPLITK;
    int tB = (tiles * (part + 1)) / SPLITK;
    int T  = tB - tA;

    auto load_tile = [&](int tk, int st) {
        int k0 = tk * BK;
        unsigned ad = asb + st * (64 * 36 * 4);
        unsigned bd = bsb + st * (64 * 36 * 4);
#pragma unroll
        for (int i = 0; i < 2; i++) {
            int idx = tid + i * 256;
            int m = idx >> 3, kc = (idx & 7) << 2;
            CPA16(ad + (m * 36 + kc) * 4, &A[(long)(row0 + m) * lda + k0 + kc]);
        }
        if (BT) {
#pragma unroll
            for (int i = 0; i < 2; i++) {
                int idx = tid + i * 256;
                int n = idx >> 3, kc = (idx & 7) << 2;
                CPA16(bd + (n * 36 + kc) * 4, &B[(long)(col0 + n) * ldb + k0 + kc]);
            }
        } else {
#pragma unroll
            for (int i = 0; i < 2; i++) {
                int idx = tid + i * 256;
                int kk = idx >> 4, nc = (idx & 15) << 2;
                CPA16(bd + (kk * 72 + nc) * 4, &B[(long)(k0 + kk) * ldb + col0 + nc]);
            }
        }
        CPCOMMIT();
    };

    if (T > 0) load_tile(tA, 0);

    for (int t = 0; t < T; t++) {
        if (t + 1 < T) { load_tile(tA + t + 1, (t + 1) & 1); CPWAIT1(); }
        else           { CPWAIT0(); }
        __syncthreads();

        const float* as = As[t & 1];
        const float* bs = Bs[t & 1];
#pragma unroll
        for (int ks = 0; ks < BK; ks += 8) {
            uint32_t ah[2][4], al[2][4];
#pragma unroll
            for (int mi = 0; mi < 2; mi++) {
                int mb = wm * 32 + mi * 16;
                split_tf32(as[(mb + g)     * 36 + ks + tg],     ah[mi][0], al[mi][0]);
                split_tf32(as[(mb + g + 8) * 36 + ks + tg],     ah[mi][1], al[mi][1]);
                split_tf32(as[(mb + g)     * 36 + ks + tg + 4], ah[mi][2], al[mi][2]);
                split_tf32(as[(mb + g + 8) * 36 + ks + tg + 4], ah[mi][3], al[mi][3]);
            }
            uint32_t bh[2][2], bl[2][2];
#pragma unroll
            for (int ni = 0; ni < 2; ni++) {
                int nb = wn * 16 + ni * 8 + g;
                float f0 = BT ? bs[nb * 36 + ks + tg]     : bs[(ks + tg)     * 72 + nb];
                float f1 = BT ? bs[nb * 36 + ks + tg + 4] : bs[(ks + tg + 4) * 72 + nb];
                split_tf32(f0, bh[ni][0], bl[ni][0]);
                split_tf32(f1, bh[ni][1], bl[ni][1]);
            }
#pragma unroll
            for (int mi = 0; mi < 2; mi++)
#pragma unroll
                for (int ni = 0; ni < 2; ni++) {
                    mma8(c[mi][ni], ah[mi], bh[ni]);
                    mma8(c[mi][ni], ah[mi], bl[ni]);
                    mma8(c[mi][ni], al[mi], bh[ni]);
                }
        }
        __syncthreads();
    }

#pragma unroll
    for (int mi = 0; mi < 2; mi++) {
#pragma unroll
        for (int ni = 0; ni < 2; ni++) {
            int row = row0 + wm * 32 + mi * 16 + g;
            int col = col0 + wn * 16 + ni * 8 + 2 * tg;
            float v0 = c[mi][ni][0] * alpha;
            float v1 = c[mi][ni][1] * alpha;
            float v2 = c[mi][ni][2] * alpha;
            float v3 = c[mi][ni][3] * alpha;
            if (EPI == 3) {
                atomicAdd(&C[(long)row * ldc + col],           v0);
                atomicAdd(&C[(long)row * ldc + col + 1],       v1);
                atomicAdd(&C[(long)(row + 8) * ldc + col],     v2);
                atomicAdd(&C[(long)(row + 8) * ldc + col + 1], v3);
            } else {
                *(float2*)&C[(long)row * ldc + col]       = make_float2(v0, v1);
                *(float2*)&C[(long)(row + 8) * ldc + col] = make_float2(v2, v3);
            }
        }
    }
}

// ---------------------------------------------------------------------------
// BM=128 x BN=64 GEMM (split tf32, 3-MMA), BT only:
//   C[m,n] = alpha * sum_k A[m,k]*B[n,k] (+bias) (+sigmoid)
// 2-stage cp.async, dynamic smem (55.3 KB). 8 warps 4m x 2n, 32x32/warp.
// B/bias/C selected by blockIdx.x / nper (fused QKV). Per-z batch strides.
// ---------------------------------------------------------------------------
#define SM128 (2 * (128 * 36 + 64 * 36) * 4)

template<int EPI>
__global__ __launch_bounds__(256)
void gemm_tc128(const float* __restrict__ A,
                const float* __restrict__ B0, const float* __restrict__ B1,
                const float* __restrict__ B2,
                const float* __restrict__ bi0, const float* __restrict__ bi1,
                const float* __restrict__ bi2,
                float* __restrict__ C0, float* __restrict__ C1, float* __restrict__ C2,
                int K, int lda, int ldb, int ldc, int nper,
                long Astride, long Bstride, long Cstride, float alpha)
{
    extern __shared__ float sm[];
    float* As = sm;                    // 2 stages x 128*36
    float* Bs = sm + 2 * 128 * 36;     // 2 stages x 64*36

    int sel = blockIdx.x / nper;
    int xb  = blockIdx.x % nper;
    const float* B    = (sel == 0) ? B0  : (sel == 1) ? B1  : B2;
    const float* bias = (sel == 0) ? bi0 : (sel == 1) ? bi1 : bi2;
    float*       C    = (sel == 0) ? C0  : (sel == 1) ? C1  : C2;

    A += (long)blockIdx.z * Astride;
    B += (long)blockIdx.z * Bstride;
    C += (long)blockIdx.z * Cstride;

    const int BK = 32;
    int tid  = threadIdx.x;
    int lane = tid & 31;
    int wid  = tid >> 5;
    int wm   = wid >> 1;              // 0..3
    int wn   = wid & 1;               // 0..1
    int g    = lane >> 2;
    int tg   = lane & 3;

    int row0 = blockIdx.y * 128;
    int col0 = xb * 64;

    unsigned asb = (unsigned)__cvta_generic_to_shared(As);
    unsigned bsb = (unsigned)__cvta_generic_to_shared(Bs);

    float c[2][4][4];
#pragma unroll
    for (int mi = 0; mi < 2; mi++)
#pragma unroll
        for (int ni = 0; ni < 4; ni++)
#pragma unroll
            for (int r = 0; r < 4; r++) c[mi][ni][r] = 0.f;

    int T = K / BK;

    auto load_tile = [&](int tk, int st) {
        int k0 = tk * BK;
        unsigned ad = asb + st * (128 * 36 * 4);
        unsigned bd = bsb + st * (64 * 36 * 4);
#pragma unroll
        for (int i = 0; i < 4; i++) {
            int idx = tid + i * 256;           // 1024 float4
            int m = idx >> 3, kc = (idx & 7) << 2;
            CPA16(ad + (m * 36 + kc) * 4, &A[(long)(row0 + m) * lda + k0 + kc]);
        }
#pragma unroll
        for (int i = 0; i < 2; i++) {
            int idx = tid + i * 256;           // 512 float4
            int n = idx >> 3, kc = (idx & 7) << 2;
            CPA16(bd + (n * 36 + kc) * 4, &B[(long)(col0 + n) * ldb + k0 + kc]);
        }
        CPCOMMIT();
    };

    load_tile(0, 0);

    for (int t = 0; t < T; t++) {
        if (t + 1 < T) { load_tile(t + 1, (t + 1) & 1); CPWAIT1(); }
        else           { CPWAIT0(); }
        __syncthreads();

        const float* as = As + (t & 1) * 128 * 36;
        const float* bs = Bs + (t & 1) * 64 * 36;
#pragma unroll
        for (int ks = 0; ks < BK; ks += 8) {
            uint32_t ah[2][4], al[2][4];
#pragma unroll
            for (int mi = 0; mi < 2; mi++) {
                int mb = wm * 32 + mi * 16;
                split_tf32(as[(mb + g)     * 36 + ks + tg],     ah[mi][0], al[mi][0]);
                split_tf32(as[(mb + g + 8) * 36 + ks + tg],     ah[mi][1], al[mi][1]);
                split_tf32(as[(mb + g)     * 36 + ks + tg + 4], ah[mi][2], al[mi][2]);
                split_tf32(as[(mb + g + 8) * 36 + ks + tg + 4], ah[mi][3], al[mi][3]);
            }
            uint32_t bh[4][2], bl[4][2];
#pragma unroll
            for (int ni = 0; ni < 4; ni++) {
                int nb = wn * 32 + ni * 8 + g;
                split_tf32(bs[nb * 36 + ks + tg],     bh[ni][0], bl[ni][0]);
                split_tf32(bs[nb * 36 + ks + tg + 4], bh[ni][1], bl[ni][1]);
            }
#pragma unroll
            for (int mi = 0; mi < 2; mi++)
#pragma unroll
                for (int ni = 0; ni < 4; ni++) {
                    mma8(c[mi][ni], ah[mi], bh[ni]);
                    mma8(c[mi][ni], ah[mi], bl[ni]);
                    mma8(c[mi][ni], al[mi], bh[ni]);
                }
        }
        __syncthreads();
    }

#pragma unroll
    for (int mi = 0; mi < 2; mi++) {
#pragma unroll
        for (int ni = 0; ni < 4; ni++) {
            int row = row0 + wm * 32 + mi * 16 + g;
            int col = col0 + wn * 32 + ni * 8 + 2 * tg;
            float v0 = c[mi][ni][0] * alpha;
            float v1 = c[mi][ni][1] * alpha;
            float v2 = c[mi][ni][2] * alpha;
            float v3 = c[mi][ni][3] * alpha;
            if (EPI >= 1) {
                float b0 = bias[col], b1 = bias[col + 1];
                v0 += b0; v1 += b1; v2 += b0; v3 += b1;
            }
            if (EPI == 2) {
                v0 = 1.f / (1.f + expf(-v0));
                v1 = 1.f / (1.f + expf(-v1));
                v2 = 1.f / (1.f + expf(-v2));
                v3 = 1.f / (1.f + expf(-v3));
            }
            *(float2*)&C[(long)row * ldc + col]       = make_float2(v0, v1);
            *(float2*)&C[(long)(row + 8) * ldc + col] = make_float2(v2, v3);
        }
    }
}

// ---------------------------------------------------------------------------
// SSM sequential scan. 16 lanes per channel (lane = state index n).
// ---------------------------------------------------------------------------
__global__ __launch_bounds__(128)
void ssm_kernel(const float* __restrict__ x, const float* __restrict__ gate,
                const float* __restrict__ Amat, const float* __restrict__ Bm,
                const float* __restrict__ Cm, const float* __restrict__ log_dt,
                float* __restrict__ Hout)
{
    int lane = threadIdx.x & 15;
    int d = blockIdx.x * (blockDim.x >> 4) + (threadIdx.x >> 4);
    if (d >= D_DIM) return;

    float Arow[N_STATE];
#pragma unroll
    for (int m = 0; m < N_STATE; m++) Arow[m] = Amat[lane * N_STATE + m];
    float Bn  = Bm[lane * D_DIM + d];
    float Cn  = Cm[d * N_STATE + lane];
    float dtd = fminf(fmaxf(expf(log_dt[d]), 1e-3f), 1e-1f);

    float h  = 0.f;
    float xv = __ldg(&x[d]);
    float gv = __ldg(&gate[d]);

    for (int t = 0; t < S_LEN; t++) {
        float xn = 0.f, gn = 0.f;
        if (t + 1 < S_LEN) {
            xn = __ldg(&x[(t + 1) * D_DIM + d]);
            gn = __ldg(&gate[(t + 1) * D_DIM + d]);
        }
        float p0 = 0.f, p1 = 0.f, p2 = 0.f, p3 = 0.f;
#pragma unroll
        for (int m = 0; m < 4; m++) {
            p0 = fmaf(Arow[m],      __shfl_sync(FULLM, h, m,      16), p0);
            p1 = fmaf(Arow[m + 4],  __shfl_sync(FULLM, h, m + 4,  16), p1);
            p2 = fmaf(Arow[m + 8],  __shfl_sync(FULLM, h, m + 8,  16), p2);
            p3 = fmaf(Arow[m + 12], __shfl_sync(FULLM, h, m + 12, 16), p3);
        }
        float acc = (p0 + p1) + (p2 + p3);
        float sc  = (acc + xv * Bn) * dtd;
        float gm  = (fabsf(sc) > SPIKE) ? gv : 0.f;
        h = fmaf(sc, gm, h);

        float pr = h * Cn;
#pragma unroll
        for (int off = 8; off; off >>= 1)
            pr += __shfl_xor_sync(FULLM, pr, off, 16);
        if (lane == 0) Hout[t * D_DIM + d] = xv + pr;

        xv = xn; gv = gn;
    }
}

// ---------------------------------------------------------------------------
// Per-row: radix-select kk-th largest |score|, local+sparse mask, softmax.
// v2: one shared 256-bin histogram per pass (4 banks, zeroed once);
// no cross-warp sum; no max subtraction (|s| bounded, no overflow risk);
// ~10 block syncs total vs ~18. Banded writes (PV reads j < (i&~63)+192).
// ---------------------------------------------------------------------------
__global__ __launch_bounds__(256)
void mask_softmax_kernel(float* __restrict__ scores)
{
    int i  = blockIdx.x;
    int hd = blockIdx.y;
    float* row = scores + ((size_t)hd * S_LEN + i) * S_LEN;

    __shared__ int   hist[4][256];
    __shared__ int   sh_sel[2];
    __shared__ float fred[8];

    int tid = threadIdx.x, lane = tid & 31, wid = tid >> 5;

    float r[8]; unsigned u[8];
    {
        float4 v0 = *(const float4*)&row[tid * 8];
        float4 v1 = *(const float4*)&row[tid * 8 + 4];
        r[0] = v0.x; r[1] = v0.y; r[2] = v0.z; r[3] = v0.w;
        r[4] = v1.x; r[5] = v1.y; r[6] = v1.z; r[7] = v1.w;
    }
#pragma unroll
    for (int e = 0; e < 8; e++) u[e] = __float_as_uint(fabsf(r[e]));

    // zero all 4 histogram banks at once (1024 ints = 256 int4)
    ((int4*)hist)[tid] = make_int4(0, 0, 0, 0);
    __syncthreads();

    unsigned prefix = 0;
    int kneed = KK;
#pragma unroll
    for (int byte = 3; byte >= 0; --byte) {
        unsigned pm = (byte == 3) ? 0u : (0xFFFFFFFFu << (8 * (byte + 1)));
        int* h = hist[byte];
#pragma unroll
        for (int e = 0; e < 8; e++)
            if ((u[e] & pm) == prefix)
                atomicAdd(&h[(u[e] >> (8 * byte)) & 255], 1);
        __syncthreads();
        if (wid == 0) {
            int v[8], cum[8], s = 0;
#pragma unroll
            for (int e = 0; e < 8; e++) {
                v[e] = h[255 - (lane * 8 + e)];
                s += v[e];
                cum[e] = s;
            }
            int incl = s;
#pragma unroll
            for (int off = 1; off < 32; off <<= 1) {
                int t2 = __shfl_up_sync(FULLM, incl, off);
                if (lane >= off) incl += t2;
            }
            int excl = incl - s;
            bool has = (excl + cum[7]) >= kneed && excl < kneed;
            unsigned bal = __ballot_sync(FULLM, has);
            int fl = __ffs(bal) - 1;
            if (lane == fl) {
                int e = 0;
                while (excl + cum[e] < kneed) e++;
                sh_sel[0] = 255 - (lane * 8 + e);
                sh_sel[1] = kneed - (excl + cum[e] - v[e]);
            }
        }
        __syncthreads();
        prefix |= ((unsigned)sh_sel[0]) << (8 * byte);
        kneed = sh_sel[1];
        // next pass writes a different hist bank; no extra sync needed
    }
    unsigned T = prefix;

    // ---- mask + exp + sum (no max subtraction: |s| small, no overflow) ----
    int jmax = i + WINDOW;
    float z = 0.f;
    float ex[8];
#pragma unroll
    for (int e = 0; e < 8; e++) {
        int j = tid * 8 + e;
        bool keep = (j <= jmax) && (u[e] >= T);
        ex[e] = keep ? __expf(r[e]) : 0.f;
        z += ex[e];
    }
#pragma unroll
    for (int off = 16; off; off >>= 1)
        z += __shfl_xor_sync(FULLM, z, off);
    if (lane == 0) fred[wid] = z;
    __syncthreads();
    float zz = 0.f;
#pragma unroll
    for (int w = 0; w < 8; w++) zz += fred[w];
    float inv = (zz > 0.f) ? 1.f / zz : 0.f;

    // PV (BM=64, band=192) only reads j < (i&~63)+192; rest stays unread.
    int limit = (i & ~63) + 192;
    if (tid * 8 < limit) {
        float4 o0 = make_float4(ex[0] * inv, ex[1] * inv, ex[2] * inv, ex[3] * inv);
        float4 o1 = make_float4(ex[4] * inv, ex[5] * inv, ex[6] * inv, ex[7] * inv);
        *(float4*)&row[tid * 8]     = o0;
        *(float4*)&row[tid * 8 + 4] = o1;
    }
}

// ---------------------------------------------------------------------------
// Launch
// ---------------------------------------------------------------------------
extern "C" void kernel_launch(void* const* d_in, const int* in_sizes, int n_in,
                              void* d_out, int out_size)
{
    const float* x      = (const float*)d_in[0];
    const float* Amat   = (const float*)d_in[1];
    const float* Bm     = (const float*)d_in[2];
    const float* Cm     = (const float*)d_in[3];
    const float* log_dt = (const float*)d_in[4];
    const float* Wg = (const float*)d_in[5];  const float* bg = (const float*)d_in[6];
    const float* Wq = (const float*)d_in[7];  const float* bq = (const float*)d_in[8];
    const float* Wk = (const float*)d_in[9];  const float* bk = (const float*)d_in[10];
    const float* Wv = (const float*)d_in[11]; const float* bv = (const float*)d_in[12];
    const float* Wd = (const float*)d_in[13]; const float* bd = (const float*)d_in[14];
    float* out = (float*)d_out;

    float *gate, *H, *Q, *K, *V, *ctx, *scores;
    cudaGetSymbolAddress((void**)&gate,   g_gate);
    cudaGetSymbolAddress((void**)&H,      g_H);
    cudaGetSymbolAddress((void**)&Q,      g_Q);
    cudaGetSymbolAddress((void**)&K,      g_K);
    cudaGetSymbolAddress((void**)&V,      g_V);
    cudaGetSymbolAddress((void**)&ctx,    g_ctx);
    cudaGetSymbolAddress((void**)&scores, g_scores);

    cudaFuncSetAttribute(gemm_tc128<0>, cudaFuncAttributeMaxDynamicSharedMemorySize, SM128);
    cudaFuncSetAttribute(gemm_tc128<1>, cudaFuncAttributeMaxDynamicSharedMemorySize, SM128);
    cudaFuncSetAttribute(gemm_tc128<2>, cudaFuncAttributeMaxDynamicSharedMemorySize, SM128);

    dim3 blk(256);

    // 1) gate = sigmoid(X Wg^T + bg)
    {
        dim3 grid(D_DIM / 64, S_LEN / 128, 1);
        gemm_tc128<2><<<grid, blk, SM128>>>(x, Wg, Wg, Wg, bg, bg, bg,
            gate, gate, gate, D_DIM, D_DIM, D_DIM, D_DIM, D_DIM / 64,
            0, 0, 0, 1.f);
    }
    // 2) SSM scan -> H = x + y
    ssm_kernel<<<D_DIM / 8, 128>>>(x, gate, Amat, Bm, Cm, log_dt, H);

    // 3) Fused Q,K,V projections
    {
        dim3 grid(3 * D_DIM / 64, S_LEN / 128, 1);
        gemm_tc128<1><<<grid, blk, SM128>>>(H, Wq, Wk, Wv, bq, bk, bv,
            Q, K, V, D_DIM, D_DIM, D_DIM, D_DIM, D_DIM / 64,
            0, 0, 0, 1.f);
    }
    // 4) scores[h] = Q_h K_h^T / 8
    {
        dim3 grid(S_LEN / 64, S_LEN / 128, N_HEADS);
        gemm_tc128<0><<<grid, blk, SM128>>>(Q, K, K, K,
            nullptr, nullptr, nullptr, scores, scores, scores,
            DH, D_DIM, D_DIM, S_LEN, S_LEN / 64,
            DH, DH, (long)S_LEN * S_LEN, 0.125f);
    }
    // 5) per-row top-k select + masks + softmax (in place, banded writes)
    {
        dim3 grid(S_LEN, N_HEADS);
        mask_softmax_kernel<<<grid, blk>>>(scores);
    }
    // 6) ctx[h] = P_h V_h   (banded, split-K=2, atomic adds)
    {
        cudaMemsetAsync(ctx, 0, (size_t)S_LEN * D_DIM * sizeof(float));
        dim3 grid(DH / 64, S_LEN / 64, N_HEADS * 2);
        gemm_tc<false, 3, 2><<<grid, blk>>>(scores, V, ctx,
            S_LEN, S_LEN, D_DIM, D_DIM,
            (long)S_LEN * S_LEN, DH, DH, 1.f, 64 + WINDOW);
    }
    // 7) out = ctx Wd^T + bd
    {
        dim3 grid(D_DIM / 64, S_LEN / 128, 1);
        gemm_tc128<1><<<grid, blk, SM128>>>(ctx, Wd, Wd, Wd, bd, bd, bd,
            out, out, out, D_DIM, D_DIM, D_DIM, D_DIM, D_DIM / 64,
            0, 0, 0, 1.f);
    }
}